// round 2
// baseline (speedup 1.0000x reference)
#include <cuda_runtime.h>
#include <math.h>
#include <stdint.h>

// Problem constants
#define D64   64
#define HH    2
#define HD    128
#define LL    3
#define NN    50000
#define GG    128
#define EE    600000
#define NE_   300000
#define NAUG  (NN + GG)          // 50128
#define M0    (EE + 2 * NN)      // 700000
#define MM    (M0 + NAUG)        // 750128
#define TAILR (MM - EE)          // 150128
#define NB_SCAN ((NAUG + 255) / 256)   // 196

#define CDIV(a, b) (((a) + (b) - 1) / (b))

// ---------------- device scratch (static, no allocs) ----------------
__device__ int    g_src[MM];
__device__ int    g_dst[MM];
__device__ int    g_deg[NAUG];
__device__ int    g_rowptr[NAUG + 1];
__device__ int    g_bsum[256];
__device__ int    g_fill[NAUG];
__device__ int    g_esrc[MM];
__device__ int    g_eid[MM];
__device__ float  g_tail[(size_t)TAILR * D64];   // e_aug rows >= EE
__device__ float  g_h[NAUG * D64];
__device__ float  g_hn[NAUG * D64];
__device__ float  g_agg[NAUG * D64];
__device__ float  g_cat[NAUG * HD];
__device__ float  g_q[NAUG * HD];
__device__ float  g_k[NAUG * HD];
__device__ float  g_v[NAUG * HD];
__device__ float  g_qp[NAUG * HD];               // qproj = q @ W2
__device__ float  g_t[NAUG * HD];
__device__ float  g_we[NAUG * HD];               // normalized weighted e sums
__device__ float  g_lh[NAUG * D64];
__device__ float  g_ln2[NAUG * D64];
__device__ float  g_ffh[NAUG * 4 * D64];
__device__ float  g_w2[HD * HD];
__device__ float  g_w3[HD * HD];
__device__ float  g_cntn[GG];
__device__ double g_lsum[GG];
__device__ double g_lsumsq[GG];
__device__ float  g_mean[GG];
__device__ float  g_rstd[GG];
__device__ int    g_abatch[NAUG];
__device__ float  g_gsum[GG * D64];

// ---------------- setup kernels ----------------
__global__ void k_build_edges(const int* __restrict__ ei0, const int* __restrict__ ei1,
                              const int* __restrict__ batch) {
    int m = blockIdx.x * blockDim.x + threadIdx.x;
    if (m >= MM) return;
    int s, d;
    if (m < EE)               { s = ei0[m]; d = ei1[m]; }
    else if (m < EE + NN)     { int i = m - EE;          s = i;             d = batch[i] + NN; }
    else if (m < EE + 2 * NN) { int i = m - EE - NN;     s = batch[i] + NN; d = i; }
    else                      { int i = m - EE - 2 * NN; s = i;             d = i; }
    g_src[m] = s; g_dst[m] = d;
    atomicAdd(&g_deg[d], 1);
}

__global__ void k_scanA() {
    __shared__ int sh[256];
    int t = threadIdx.x;
    int i = blockIdx.x * 256 + t;
    int v = (i < NAUG) ? g_deg[i] : 0;
    sh[t] = v;
    __syncthreads();
    for (int off = 1; off < 256; off <<= 1) {
        int a = (t >= off) ? sh[t - off] : 0;
        __syncthreads();
        sh[t] += a;
        __syncthreads();
    }
    if (i < NAUG) g_rowptr[i] = sh[t] - v;   // intra-block exclusive
    if (t == 255) g_bsum[blockIdx.x] = sh[255];
}

__global__ void k_scanB() {
    __shared__ int sh[256];
    int t = threadIdx.x;
    int v = (t < NB_SCAN) ? g_bsum[t] : 0;
    sh[t] = v;
    __syncthreads();
    for (int off = 1; off < 256; off <<= 1) {
        int a = (t >= off) ? sh[t - off] : 0;
        __syncthreads();
        sh[t] += a;
        __syncthreads();
    }
    if (t < NB_SCAN) g_bsum[t] = sh[t] - v;  // exclusive
}

__global__ void k_scanC() {
    int i = blockIdx.x * 256 + threadIdx.x;
    if (i < NAUG) {
        int r = g_rowptr[i] + g_bsum[i >> 8];
        g_rowptr[i] = r;
        g_fill[i] = r;
    }
    if (i == 0) g_rowptr[NAUG] = MM;
}

__global__ void k_scatter() {
    int m = blockIdx.x * blockDim.x + threadIdx.x;
    if (m >= MM) return;
    int pos = atomicAdd(&g_fill[g_dst[m]], 1);
    g_esrc[pos] = g_src[m];
    g_eid[pos]  = m;
}

__global__ void k_abatch(const int* __restrict__ batch) {
    int i = blockIdx.x * blockDim.x + threadIdx.x;
    if (i >= NAUG) return;
    g_abatch[i] = (i < NN) ? batch[i] : (i - NN);
}

__global__ void k_cntn(const int* __restrict__ batch) {
    int i = blockIdx.x * blockDim.x + threadIdx.x;
    if (i >= NN) return;
    atomicAdd(&g_cntn[batch[i]], 1.f);
}

__global__ void k_init_h(const float* __restrict__ x, const float* __restrict__ cond) {
    int idx = blockIdx.x * blockDim.x + threadIdx.x;
    if (idx >= NAUG * D64) return;
    g_h[idx] = (idx < NN * D64) ? x[idx] : cond[idx - NN * D64];
}

__global__ void k_tail_ep() {
    int idx = blockIdx.x * blockDim.x + threadIdx.x;
    if (idx >= 2 * NN * D64) return;
    g_tail[idx] = ((idx & 63) == 0) ? 1.f : 0.f;
}

// loop_attr for node i: mean over non-loop incoming edges of e_base
__global__ void k_tail_csr(const float* __restrict__ edge_attr) {
    int i = (blockIdx.x * blockDim.x + threadIdx.x) >> 5;
    int lane = threadIdx.x & 31;
    if (i >= NAUG) return;
    float2 acc = {0.f, 0.f};
    float cnt = 0.f;
    int e0 = g_rowptr[i], e1 = g_rowptr[i + 1];
    for (int e = e0; e < e1; e++) {
        int m = g_eid[e];
        if (m < EE) {
            float2 ev = ((const float2*)(edge_attr + (size_t)m * D64))[lane];
            acc.x += ev.x; acc.y += ev.y;
            cnt += 1.f;
        } else if (m < M0) {
            if (lane == 0) acc.x += 1.f;   // e_p row: dim0 only
            cnt += 1.f;
        }
    }
    float invc = 1.f / fmaxf(cnt, 1.f);
    float2 o = {acc.x * invc, acc.y * invc};
    ((float2*)(g_tail + (size_t)(2 * NN + i) * D64))[lane] = o;
}

// ---------------- graph layernorm ----------------
__global__ void k_ln_stats(const float* __restrict__ X) {
    int i = (blockIdx.x * blockDim.x + threadIdx.x) >> 5;
    int lane = threadIdx.x & 31;
    if (i >= NAUG) return;
    float2 v = ((const float2*)(X + (size_t)i * D64))[lane];
    float s  = v.x + v.y;
    float ss = v.x * v.x + v.y * v.y;
#pragma unroll
    for (int off = 16; off; off >>= 1) {
        s  += __shfl_xor_sync(0xffffffffu, s, off);
        ss += __shfl_xor_sync(0xffffffffu, ss, off);
    }
    if (lane == 0) {
        int b = g_abatch[i];
        atomicAdd(&g_lsum[b], (double)s);
        atomicAdd(&g_lsumsq[b], (double)ss);
    }
}

__global__ void k_ln_final() {
    int g = threadIdx.x;
    if (g >= GG) return;
    double norm = (double)fmaxf(g_cntn[g] + 1.f, 1.f) * D64;
    double mean = g_lsum[g] / norm;
    double var  = g_lsumsq[g] / norm - mean * mean;
    g_mean[g] = (float)mean;
    g_rstd[g] = rsqrtf((float)var + 1e-5f);
}

// writes hn AND cat[:, :64]
__global__ void k_ln_apply2(const float* __restrict__ X) {
    int idx = blockIdx.x * blockDim.x + threadIdx.x;
    if (idx >= NAUG * D64) return;
    int i = idx >> 6, d = idx & 63;
    int b = g_abatch[i];
    float v = (X[idx] - g_mean[b]) * g_rstd[b];
    g_hn[idx] = v;
    g_cat[(size_t)i * HD + d] = v;
}

__global__ void k_ln_apply(const float* __restrict__ X, float* __restrict__ Y) {
    int idx = blockIdx.x * blockDim.x + threadIdx.x;
    if (idx >= NAUG * D64) return;
    int b = g_abatch[idx >> 6];
    Y[idx] = (X[idx] - g_mean[b]) * g_rstd[b];
}

// ---------------- gen_conv: CSR gather, no atomics ----------------
__global__ void k_gen_csr(const float* __restrict__ edge_attr) {
    int i = (blockIdx.x * blockDim.x + threadIdx.x) >> 5;
    int lane = threadIdx.x & 31;
    if (i >= NAUG) return;
    float2 acc = {0.f, 0.f};
    int e0 = g_rowptr[i], e1 = g_rowptr[i + 1];
    for (int e = e0; e < e1; e++) {
        int s = g_esrc[e], m = g_eid[e];
        const float* ep = (m < EE) ? edge_attr + (size_t)m * D64
                                   : g_tail + (size_t)(m - EE) * D64;
        float2 ev = ((const float2*)ep)[lane];
        float2 hv = ((const float2*)(g_hn + (size_t)s * D64))[lane];
        acc.x += fmaxf(hv.x + ev.x, 0.f) + 1e-7f;
        acc.y += fmaxf(hv.y + ev.y, 0.f) + 1e-7f;
    }
    float2 hi = ((const float2*)(g_hn + (size_t)i * D64))[lane];
    float2 o = {acc.x + hi.x, acc.y + hi.y};
    ((float2*)(g_agg + (size_t)i * D64))[lane] = o;
}

// ---------------- fused attention: CSR, two register passes, no atomics ----------------
__global__ void k_attn_csr(const float* __restrict__ edge_attr) {
    int i = (blockIdx.x * blockDim.x + threadIdx.x) >> 5;
    int lane = threadIdx.x & 31;
    if (i >= NAUG) return;
    int el = lane & 15;
    float4 q4  = *(const float4*)(g_q  + (size_t)i * HD + 4 * lane);
    float4 qp4 = *(const float4*)(g_qp + (size_t)i * HD + 4 * lane);
    int e0 = g_rowptr[i], e1 = g_rowptr[i + 1];

    // pass 1: segment max of alpha
    float mx = -INFINITY;
    for (int e = e0; e < e1; e++) {
        int s = g_esrc[e], m = g_eid[e];
        const float* ep = (m < EE) ? edge_attr + (size_t)m * D64
                                   : g_tail + (size_t)(m - EE) * D64;
        float4 k4 = *(const float4*)(g_k + (size_t)s * HD + 4 * lane);
        float4 e4 = *(const float4*)(ep + 4 * el);
        float p = q4.x * k4.x + q4.y * k4.y + q4.z * k4.z + q4.w * k4.w
                + qp4.x * e4.x + qp4.y * e4.y + qp4.z * e4.z + qp4.w * e4.w;
        p += __shfl_xor_sync(0xffffffffu, p, 1);
        p += __shfl_xor_sync(0xffffffffu, p, 2);
        p += __shfl_xor_sync(0xffffffffu, p, 4);
        p += __shfl_xor_sync(0xffffffffu, p, 8);
        mx = fmaxf(mx, p * 0.125f);
    }

    // pass 2: exp-weighted accumulation (normalize at the end)
    float sum = 0.f;
    float4 vacc = {0.f, 0.f, 0.f, 0.f};
    float4 eacc = {0.f, 0.f, 0.f, 0.f};
    for (int e = e0; e < e1; e++) {
        int s = g_esrc[e], m = g_eid[e];
        const float* ep = (m < EE) ? edge_attr + (size_t)m * D64
                                   : g_tail + (size_t)(m - EE) * D64;
        float4 k4 = *(const float4*)(g_k + (size_t)s * HD + 4 * lane);
        float4 e4 = *(const float4*)(ep + 4 * el);
        float p = q4.x * k4.x + q4.y * k4.y + q4.z * k4.z + q4.w * k4.w
                + qp4.x * e4.x + qp4.y * e4.y + qp4.z * e4.z + qp4.w * e4.w;
        p += __shfl_xor_sync(0xffffffffu, p, 1);
        p += __shfl_xor_sync(0xffffffffu, p, 2);
        p += __shfl_xor_sync(0xffffffffu, p, 4);
        p += __shfl_xor_sync(0xffffffffu, p, 8);
        float w = expf(p * 0.125f - mx);
        sum += w;
        float4 v4 = *(const float4*)(g_v + (size_t)s * HD + 4 * lane);
        vacc.x += w * v4.x; vacc.y += w * v4.y; vacc.z += w * v4.z; vacc.w += w * v4.w;
        eacc.x += w * e4.x; eacc.y += w * e4.y; eacc.z += w * e4.z; eacc.w += w * e4.w;
    }
    float inv = 1.f / (sum + 1e-16f);
    float4 to = {vacc.x * inv, vacc.y * inv, vacc.z * inv, vacc.w * inv};
    float4 wo = {eacc.x * inv, eacc.y * inv, eacc.z * inv, eacc.w * inv};
    *(float4*)(g_t  + (size_t)i * HD + 4 * lane) = to;
    *(float4*)(g_we + (size_t)i * HD + 4 * lane) = wo;
}

// ---------------- block-diagonal weight builders ----------------
// W2: qproj[i, h*64+c] = sum_d q[i, h*64+d] * ew[c, h*64+d]
__global__ void k_build_w2(const float* __restrict__ ew) {
    int idx = blockIdx.x * blockDim.x + threadIdx.x;
    if (idx >= HD * HD) return;
    int r = idx >> 7, o = idx & 127;
    int h = r >> 6, d = r & 63, h2 = o >> 6, c = o & 63;
    g_w2[idx] = (h == h2) ? ew[(size_t)c * HD + h * 64 + d] : 0.f;
}
// W3: epi[i, h*64+o2] = sum_c we[i, h*64+c] * ew[c, h*64+o2]
__global__ void k_build_w3(const float* __restrict__ ew) {
    int idx = blockIdx.x * blockDim.x + threadIdx.x;
    if (idx >= HD * HD) return;
    int r = idx >> 7, o = idx & 127;
    int h = r >> 6, c = r & 63, h2 = o >> 6, o2 = o & 63;
    g_w3[idx] = (h == h2) ? ew[(size_t)c * HD + h2 * 64 + o2] : 0.f;
}

// ---------------- tiled GEMM: C = act(A@W + b) [+= if ACCUM], 64 rows/block ----------------
template <int IN, int OUT, int ACT, int ACCUM>
__global__ __launch_bounds__(256) void k_gemm(
        const float* __restrict__ A, const float* __restrict__ W,
        const float* __restrict__ bias, float* __restrict__ C,
        int ldc, int rows) {
    __shared__ float As[64][33];
    __shared__ float Ws[32][OUT];
    const int tx = threadIdx.x & 31;
    const int ty = threadIdx.x >> 5;   // 0..7
    const int r0 = blockIdx.x * 64;
    constexpr int JN = OUT / 32;
    float acc[8][JN];
#pragma unroll
    for (int i = 0; i < 8; i++)
#pragma unroll
        for (int j = 0; j < JN; j++) acc[i][j] = 0.f;

    for (int k0 = 0; k0 < IN; k0 += 32) {
#pragma unroll
        for (int t = 0; t < 8; t++) {
            int li = threadIdx.x + t * 256;   // 0..2047
            int rr = li >> 5, kk = li & 31;
            int row = r0 + rr;
            As[rr][kk] = (row < rows) ? A[(size_t)row * IN + k0 + kk] : 0.f;
        }
#pragma unroll
        for (int t = 0; t < (32 * OUT) / 256; t++) {
            int li = threadIdx.x + t * 256;
            int kk = li / OUT, oo = li % OUT;
            Ws[kk][oo] = W[(size_t)(k0 + kk) * OUT + oo];
        }
        __syncthreads();
#pragma unroll
        for (int kk = 0; kk < 32; kk++) {
            float wv[JN];
#pragma unroll
            for (int j = 0; j < JN; j++) wv[j] = Ws[kk][tx + 32 * j];
#pragma unroll
            for (int i = 0; i < 8; i++) {
                float a = As[ty * 8 + i][kk];
#pragma unroll
                for (int j = 0; j < JN; j++) acc[i][j] += a * wv[j];
            }
        }
        __syncthreads();
    }
#pragma unroll
    for (int i = 0; i < 8; i++) {
        int row = r0 + ty * 8 + i;
        if (row >= rows) continue;
#pragma unroll
        for (int j = 0; j < JN; j++) {
            int o = tx + 32 * j;
            float v = acc[i][j] + (bias ? bias[o] : 0.f);
            if (ACT == 1) v = (v > 0.f) ? v : 0.01f * v;
            float* cp = &C[(size_t)row * ldc + o];
            if (ACCUM) *cp += v; else *cp = v;
        }
    }
}

// ---------------- outputs ----------------
__global__ void k_glob_sum(const int* __restrict__ batch) {
    int idx = blockIdx.x * blockDim.x + threadIdx.x;
    if (idx >= NN * D64) return;
    atomicAdd(&g_gsum[batch[idx >> 6] * D64 + (idx & 63)], g_h[idx]);
}

__global__ void k_glob_out(float* __restrict__ out) {
    int idx = blockIdx.x * blockDim.x + threadIdx.x;
    if (idx >= GG * D64) return;
    int g = idx >> 6;
    out[NN * D64 + idx] = g_gsum[idx] / fmaxf(g_cntn[g], 1.f) + g_h[NN * D64 + idx];
}

__global__ void k_ne_out(const int* __restrict__ ne0, const int* __restrict__ ne1,
                         float* __restrict__ out) {
    int idx = blockIdx.x * blockDim.x + threadIdx.x;
    if (idx >= NE_ * D64) return;
    int j = idx >> 6, d = idx & 63;
    out[(NN + GG) * D64 + idx] = g_h[ne0[j] * D64 + d] + g_h[ne1[j] * D64 + d];
}

// ---------------- host launcher ----------------
#define GETSYM(ptr, sym) do { void* _p; cudaGetSymbolAddress(&_p, sym); ptr = (decltype(ptr))_p; } while (0)

extern "C" void kernel_launch(void* const* d_in, const int* in_sizes, int n_in,
                              void* d_out, int out_size) {
    const float* x          = (const float*)d_in[0];
    const float* cond       = (const float*)d_in[1];
    const float* edge_attr  = (const float*)d_in[2];
    const int*   edge_index = (const int*)d_in[3];
    const int*   ne_index   = (const int*)d_in[4];
    const int*   batch      = (const int*)d_in[5];
    const float* gen_w  = (const float*)d_in[6];
    const float* gen_b  = (const float*)d_in[7];
    const float* q_w    = (const float*)d_in[8];
    const float* q_b    = (const float*)d_in[9];
    const float* k_w    = (const float*)d_in[10];
    const float* k_b    = (const float*)d_in[11];
    const float* v_w    = (const float*)d_in[12];
    const float* v_b    = (const float*)d_in[13];
    const float* e_w    = (const float*)d_in[14];
    const float* skip_w = (const float*)d_in[15];
    const float* skip_b = (const float*)d_in[16];
    const float* lin_w  = (const float*)d_in[17];
    const float* lin_b  = (const float*)d_in[18];
    const float* ff_w1  = (const float*)d_in[19];
    const float* ff_b1  = (const float*)d_in[20];
    const float* ff_w2  = (const float*)d_in[21];
    const float* ff_b2  = (const float*)d_in[22];
    float* out = (float*)d_out;

    float *h_p, *hn_p, *agg_p, *cat_p, *q_p, *k_p, *v_p, *qp_p, *t_p, *we_p;
    float *lh_p, *ln2_p, *ffh_p, *cntn_p, *gsum_p, *w2_p, *w3_p;
    int   *deg_p;
    double *lsum_p, *lsumsq_p;
    GETSYM(h_p, g_h);     GETSYM(hn_p, g_hn);   GETSYM(agg_p, g_agg);
    GETSYM(cat_p, g_cat); GETSYM(q_p, g_q);     GETSYM(k_p, g_k);
    GETSYM(v_p, g_v);     GETSYM(qp_p, g_qp);   GETSYM(t_p, g_t);
    GETSYM(we_p, g_we);   GETSYM(lh_p, g_lh);   GETSYM(ln2_p, g_ln2);
    GETSYM(ffh_p, g_ffh); GETSYM(cntn_p, g_cntn); GETSYM(gsum_p, g_gsum);
    GETSYM(w2_p, g_w2);   GETSYM(w3_p, g_w3);   GETSYM(deg_p, g_deg);
    GETSYM(lsum_p, g_lsum); GETSYM(lsumsq_p, g_lsumsq);

    const int T = 256;
    cudaStream_t st = 0;

    // ---- setup: CSR build + aux ----
    cudaMemsetAsync(deg_p,  0, sizeof(int) * NAUG, st);
    cudaMemsetAsync(cntn_p, 0, sizeof(float) * GG, st);
    cudaMemsetAsync(gsum_p, 0, sizeof(float) * GG * D64, st);

    k_build_edges<<<CDIV(MM, T), T, 0, st>>>(edge_index, edge_index + EE, batch);
    k_scanA<<<NB_SCAN, 256, 0, st>>>();
    k_scanB<<<1, 256, 0, st>>>();
    k_scanC<<<NB_SCAN, 256, 0, st>>>();
    k_scatter<<<CDIV(MM, T), T, 0, st>>>();
    k_abatch<<<CDIV(NAUG, T), T, 0, st>>>(batch);
    k_cntn<<<CDIV(NN, T), T, 0, st>>>(batch);
    k_init_h<<<CDIV(NAUG * D64, T), T, 0, st>>>(x, cond);
    k_tail_ep<<<CDIV(2 * NN * D64, T), T, 0, st>>>();
    k_tail_csr<<<CDIV(NAUG * 32, T), T, 0, st>>>(edge_attr);

    // ---- layers ----
    for (int i = 0; i < LL; i++) {
        const float* gw  = gen_w  + (size_t)i * D64 * D64;
        const float* gb  = gen_b  + (size_t)i * D64;
        const float* qw  = q_w    + (size_t)i * HD * HD;
        const float* qb  = q_b    + (size_t)i * HD;
        const float* kw  = k_w    + (size_t)i * HD * HD;
        const float* kb  = k_b    + (size_t)i * HD;
        const float* vw  = v_w    + (size_t)i * HD * HD;
        const float* vb  = v_b    + (size_t)i * HD;
        const float* ew  = e_w    + (size_t)i * D64 * HD;
        const float* sw  = skip_w + (size_t)i * HD * HD;
        const float* sb  = skip_b + (size_t)i * HD;
        const float* lw  = lin_w  + (size_t)i * HD * D64;
        const float* lb  = lin_b  + (size_t)i * D64;
        const float* f1w = ff_w1  + (size_t)i * D64 * 4 * D64;
        const float* f1b = ff_b1  + (size_t)i * 4 * D64;
        const float* f2w = ff_w2  + (size_t)i * 4 * D64 * D64;
        const float* f2b = ff_b2  + (size_t)i * D64;

        // LN1 -> hn (+ cat left half)
        cudaMemsetAsync(lsum_p,   0, sizeof(double) * GG, st);
        cudaMemsetAsync(lsumsq_p, 0, sizeof(double) * GG, st);
        k_ln_stats<<<CDIV(NAUG * 32, T), T, 0, st>>>(h_p);
        k_ln_final<<<1, GG, 0, st>>>();
        k_ln_apply2<<<CDIV(NAUG * D64, T), T, 0, st>>>(h_p);

        // gen_conv (CSR) -> agg ; gemm -> cat right half
        k_gen_csr<<<CDIV(NAUG * 32, T), T, 0, st>>>(edge_attr);
        k_gemm<D64, D64, 0, 0><<<CDIV(NAUG, 64), T, 0, st>>>(agg_p, gw, gb, cat_p + D64, HD, NAUG);

        // q, k, v projections
        k_gemm<HD, HD, 0, 0><<<CDIV(NAUG, 64), T, 0, st>>>(cat_p, qw, qb, q_p, HD, NAUG);
        k_gemm<HD, HD, 0, 0><<<CDIV(NAUG, 64), T, 0, st>>>(cat_p, kw, kb, k_p, HD, NAUG);
        k_gemm<HD, HD, 0, 0><<<CDIV(NAUG, 64), T, 0, st>>>(cat_p, vw, vb, v_p, HD, NAUG);

        // qproj = q @ W2 (block-diag rearranged e_w)
        k_build_w2<<<CDIV(HD * HD, T), T, 0, st>>>(ew);
        k_build_w3<<<CDIV(HD * HD, T), T, 0, st>>>(ew);
        k_gemm<HD, HD, 0, 0><<<CDIV(NAUG, 64), T, 0, st>>>(q_p, w2_p, nullptr, qp_p, HD, NAUG);

        // fused attention (CSR): t = normalized weighted v sum, we = weighted e sum
        k_attn_csr<<<CDIV(NAUG * 32, T), T, 0, st>>>(edge_attr);

        // t += cat @ skip_w + skip_b ; t += we @ W3
        k_gemm<HD, HD, 0, 1><<<CDIV(NAUG, 64), T, 0, st>>>(cat_p, sw, sb, t_p, HD, NAUG);
        k_gemm<HD, HD, 0, 1><<<CDIV(NAUG, 64), T, 0, st>>>(we_p, w3_p, nullptr, t_p, HD, NAUG);

        // lin
        k_gemm<HD, D64, 0, 0><<<CDIV(NAUG, 64), T, 0, st>>>(t_p, lw, lb, lh_p, D64, NAUG);

        // LN2
        cudaMemsetAsync(lsum_p,   0, sizeof(double) * GG, st);
        cudaMemsetAsync(lsumsq_p, 0, sizeof(double) * GG, st);
        k_ln_stats<<<CDIV(NAUG * 32, T), T, 0, st>>>(lh_p);
        k_ln_final<<<1, GG, 0, st>>>();
        k_ln_apply<<<CDIV(NAUG * D64, T), T, 0, st>>>(lh_p, ln2_p);

        // FF + residual
        k_gemm<D64, 4 * D64, 1, 0><<<CDIV(NAUG, 64), T, 0, st>>>(ln2_p, f1w, f1b, ffh_p, 4 * D64, NAUG);
        k_gemm<4 * D64, D64, 0, 1><<<CDIV(NAUG, 64), T, 0, st>>>(ffh_p, f2w, f2b, h_p, D64, NAUG);
    }

    // ---- outputs ----
    cudaMemcpyAsync(out, h_p, sizeof(float) * NN * D64, cudaMemcpyDeviceToDevice, st);
    k_glob_sum<<<CDIV(NN * D64, T), T, 0, st>>>(batch);
    k_glob_out<<<CDIV(GG * D64, T), T, 0, st>>>(out);
    k_ne_out<<<CDIV(NE_ * D64, T), T, 0, st>>>(ne_index, ne_index + NE_, out);
}

// round 3
// speedup vs baseline: 1.6088x; 1.6088x over previous
#include <cuda_runtime.h>
#include <math.h>
#include <stdint.h>

// Problem constants
#define D64   64
#define HH    2
#define HD    128
#define LL    3
#define NN    50000
#define GG    128
#define EE    600000
#define NE_   300000
#define NAUG  (NN + GG)          // 50128
#define M0    (EE + 2 * NN)      // 700000
#define MM    (M0 + NAUG)        // 750128
#define TAILR (MM - EE)          // 150128
#define NB_SCAN ((NAUG + 255) / 256)   // 196

#define CDIV(a, b) (((a) + (b) - 1) / (b))

// ---------------- device scratch (static, no allocs) ----------------
__device__ int    g_src[MM];
__device__ int    g_dst[MM];
__device__ int    g_deg[NAUG];
__device__ int    g_rowptr[NAUG + 1];
__device__ int    g_bsum[256];
__device__ int    g_fill[NAUG];
__device__ int    g_esrc[MM];
__device__ int    g_eid[MM];
__device__ float  g_alpha[(size_t)MM * HH];
__device__ float  g_tail[(size_t)TAILR * D64];   // e_aug rows >= EE
__device__ float  g_h[NAUG * D64];
__device__ float  g_hn[NAUG * D64];
__device__ float  g_agg[NAUG * D64];
__device__ float  g_cat[NAUG * HD];
__device__ float  g_q[NAUG * HD];
__device__ float  g_k[NAUG * HD];
__device__ float  g_v[NAUG * HD];
__device__ float  g_qp[NAUG * HD];               // qproj = q @ W2
__device__ float  g_t[NAUG * HD];                // attention V output
__device__ float  g_we[NAUG * HD];               // normalized weighted e sums
__device__ float  g_lh[NAUG * D64];
__device__ float  g_ln2[NAUG * D64];
__device__ float  g_ffh[NAUG * 4 * D64];
__device__ float  g_w2[HD * HD];
__device__ float  g_w3[HD * HD];
__device__ float  g_swlw[HD * D64];
__device__ float  g_lw3[HD * D64];
__device__ float  g_blb[D64];
__device__ float  g_mmax[NAUG * HH];
__device__ float  g_cntn[GG];
__device__ double g_lsum[GG];
__device__ double g_lsumsq[GG];
__device__ float  g_mean[GG];
__device__ float  g_rstd[GG];
__device__ int    g_abatch[NAUG];
__device__ float  g_gsum[GG * D64];

// ---------------- setup kernels ----------------
__global__ void k_build_edges(const int* __restrict__ ei0, const int* __restrict__ ei1,
                              const int* __restrict__ batch) {
    int m = blockIdx.x * blockDim.x + threadIdx.x;
    if (m >= MM) return;
    int s, d;
    if (m < EE)               { s = ei0[m]; d = ei1[m]; }
    else if (m < EE + NN)     { int i = m - EE;          s = i;             d = batch[i] + NN; }
    else if (m < EE + 2 * NN) { int i = m - EE - NN;     s = batch[i] + NN; d = i; }
    else                      { int i = m - EE - 2 * NN; s = i;             d = i; }
    g_src[m] = s; g_dst[m] = d;
    atomicAdd(&g_deg[d], 1);
}

__global__ void k_scanA() {
    __shared__ int sh[256];
    int t = threadIdx.x;
    int i = blockIdx.x * 256 + t;
    int v = (i < NAUG) ? g_deg[i] : 0;
    sh[t] = v;
    __syncthreads();
    for (int off = 1; off < 256; off <<= 1) {
        int a = (t >= off) ? sh[t - off] : 0;
        __syncthreads();
        sh[t] += a;
        __syncthreads();
    }
    if (i < NAUG) g_rowptr[i] = sh[t] - v;
    if (t == 255) g_bsum[blockIdx.x] = sh[255];
}

__global__ void k_scanB() {
    __shared__ int sh[256];
    int t = threadIdx.x;
    int v = (t < NB_SCAN) ? g_bsum[t] : 0;
    sh[t] = v;
    __syncthreads();
    for (int off = 1; off < 256; off <<= 1) {
        int a = (t >= off) ? sh[t - off] : 0;
        __syncthreads();
        sh[t] += a;
        __syncthreads();
    }
    if (t < NB_SCAN) g_bsum[t] = sh[t] - v;
}

__global__ void k_scanC() {
    int i = blockIdx.x * 256 + threadIdx.x;
    if (i < NAUG) {
        int r = g_rowptr[i] + g_bsum[i >> 8];
        g_rowptr[i] = r;
        g_fill[i] = r;
        g_deg[i] = 0;                 // self-clean for next launch
    }
    if (i == 0) g_rowptr[NAUG] = MM;
}

__global__ void k_scatter() {
    int m = blockIdx.x * blockDim.x + threadIdx.x;
    if (m >= MM) return;
    int pos = atomicAdd(&g_fill[g_dst[m]], 1);
    g_esrc[pos] = g_src[m];
    g_eid[pos]  = m;
}

__global__ void k_abatch(const int* __restrict__ batch) {
    int i = blockIdx.x * blockDim.x + threadIdx.x;
    if (i >= NAUG) return;
    g_abatch[i] = (i < NN) ? batch[i] : (i - NN);
}

__global__ void k_cntn(const int* __restrict__ batch) {
    int i = blockIdx.x * blockDim.x + threadIdx.x;
    if (i >= NN) return;
    atomicAdd(&g_cntn[batch[i]], 1.f);
}

__global__ void k_init_h(const float* __restrict__ x, const float* __restrict__ cond) {
    int idx = blockIdx.x * blockDim.x + threadIdx.x;
    if (idx >= NAUG * D64) return;
    g_h[idx] = (idx < NN * D64) ? x[idx] : cond[idx - NN * D64];
}

__global__ void k_tail_ep() {
    int idx = blockIdx.x * blockDim.x + threadIdx.x;
    if (idx >= 2 * NN * D64) return;
    g_tail[idx] = ((idx & 63) == 0) ? 1.f : 0.f;
}

__global__ void k_tail_csr(const float* __restrict__ edge_attr) {
    int i = (blockIdx.x * blockDim.x + threadIdx.x) >> 5;
    int lane = threadIdx.x & 31;
    if (i >= NAUG) return;
    float2 acc = {0.f, 0.f};
    float cnt = 0.f;
    int e0 = g_rowptr[i], e1 = g_rowptr[i + 1];
    for (int e = e0; e < e1; e++) {
        int m = g_eid[e];
        if (m < EE) {
            float2 ev = ((const float2*)(edge_attr + (size_t)m * D64))[lane];
            acc.x += ev.x; acc.y += ev.y;
            cnt += 1.f;
        } else if (m < M0) {
            if (lane == 0) acc.x += 1.f;
            cnt += 1.f;
        }
    }
    float invc = 1.f / fmaxf(cnt, 1.f);
    float2 o = {acc.x * invc, acc.y * invc};
    ((float2*)(g_tail + (size_t)(2 * NN + i) * D64))[lane] = o;
}

// ---------------- graph layernorm ----------------
__global__ void k_ln_stats(const float* __restrict__ X) {
    int i = (blockIdx.x * blockDim.x + threadIdx.x) >> 5;
    int lane = threadIdx.x & 31;
    if (i >= NAUG) return;
    float2 v = ((const float2*)(X + (size_t)i * D64))[lane];
    float s  = v.x + v.y;
    float ss = v.x * v.x + v.y * v.y;
#pragma unroll
    for (int off = 16; off; off >>= 1) {
        s  += __shfl_xor_sync(0xffffffffu, s, off);
        ss += __shfl_xor_sync(0xffffffffu, ss, off);
    }
    if (lane == 0) {
        int b = g_abatch[i];
        atomicAdd(&g_lsum[b], (double)s);
        atomicAdd(&g_lsumsq[b], (double)ss);
    }
}

__global__ void k_ln_final() {
    int g = threadIdx.x;
    if (g >= GG) return;
    double norm = (double)fmaxf(g_cntn[g] + 1.f, 1.f) * D64;
    double mean = g_lsum[g] / norm;
    double var  = g_lsumsq[g] / norm - mean * mean;
    g_mean[g] = (float)mean;
    g_rstd[g] = rsqrtf((float)var + 1e-5f);
    g_lsum[g] = 0.0;            // self-clean
    g_lsumsq[g] = 0.0;
}

__global__ void k_ln_apply2(const float* __restrict__ X) {
    int idx = blockIdx.x * blockDim.x + threadIdx.x;
    if (idx >= NAUG * D64) return;
    int i = idx >> 6, d = idx & 63;
    int b = g_abatch[i];
    float v = (X[idx] - g_mean[b]) * g_rstd[b];
    g_hn[idx] = v;
    g_cat[(size_t)i * HD + d] = v;
}

__global__ void k_ln_apply(const float* __restrict__ X, float* __restrict__ Y) {
    int idx = blockIdx.x * blockDim.x + threadIdx.x;
    if (idx >= NAUG * D64) return;
    int b = g_abatch[idx >> 6];
    Y[idx] = (X[idx] - g_mean[b]) * g_rstd[b];
}

// ---------------- gen_conv: regular nodes (warp each) ----------------
__global__ void k_gen(const float* __restrict__ edge_attr) {
    int i = (blockIdx.x * blockDim.x + threadIdx.x) >> 5;
    int lane = threadIdx.x & 31;
    if (i >= NN) return;
    float2 acc = {0.f, 0.f};
    int e0 = g_rowptr[i], e1 = g_rowptr[i + 1];
    for (int e = e0; e < e1; e++) {
        int s = g_esrc[e], m = g_eid[e];
        const float* ep = (m < EE) ? edge_attr + (size_t)m * D64
                                   : g_tail + (size_t)(m - EE) * D64;
        float2 ev = ((const float2*)ep)[lane];
        float2 hv = ((const float2*)(g_hn + (size_t)s * D64))[lane];
        acc.x += fmaxf(hv.x + ev.x, 0.f) + 1e-7f;
        acc.y += fmaxf(hv.y + ev.y, 0.f) + 1e-7f;
    }
    float2 hi = ((const float2*)(g_hn + (size_t)i * D64))[lane];
    float2 o = {acc.x + hi.x, acc.y + hi.y};
    ((float2*)(g_agg + (size_t)i * D64))[lane] = o;
}

// gen_conv: virtual nodes (block each)
__global__ void k_gen_v(const float* __restrict__ edge_attr) {
    __shared__ float sa[64];
    int i = NN + blockIdx.x;
    int tid = threadIdx.x, lane = tid & 31, wid = tid >> 5;
    if (tid < 64) sa[tid] = 0.f;
    __syncthreads();
    int e0 = g_rowptr[i], e1 = g_rowptr[i + 1];
    float2 acc = {0.f, 0.f};
    for (int e = e0 + wid; e < e1; e += 8) {
        int s = g_esrc[e], m = g_eid[e];
        const float* ep = (m < EE) ? edge_attr + (size_t)m * D64
                                   : g_tail + (size_t)(m - EE) * D64;
        float2 ev = ((const float2*)ep)[lane];
        float2 hv = ((const float2*)(g_hn + (size_t)s * D64))[lane];
        acc.x += fmaxf(hv.x + ev.x, 0.f) + 1e-7f;
        acc.y += fmaxf(hv.y + ev.y, 0.f) + 1e-7f;
    }
    atomicAdd(&sa[2 * lane],     acc.x);
    atomicAdd(&sa[2 * lane + 1], acc.y);
    __syncthreads();
    if (tid < 64) g_agg[(size_t)i * D64 + tid] = sa[tid] + g_hn[(size_t)i * D64 + tid];
}

// ---------------- attention pass 1: alpha + segment max ----------------
__global__ void k_attn1(const float* __restrict__ edge_attr) {
    int i = (blockIdx.x * blockDim.x + threadIdx.x) >> 5;
    int lane = threadIdx.x & 31;
    if (i >= NN) return;
    int el = lane & 15;
    float4 q4  = *(const float4*)(g_q  + (size_t)i * HD + 4 * lane);
    float4 qp4 = *(const float4*)(g_qp + (size_t)i * HD + 4 * lane);
    int e0 = g_rowptr[i], e1 = g_rowptr[i + 1];
    float mx = -INFINITY;
    for (int e = e0; e < e1; e++) {
        int s = g_esrc[e], m = g_eid[e];
        const float* ep = (m < EE) ? edge_attr + (size_t)m * D64
                                   : g_tail + (size_t)(m - EE) * D64;
        float4 k4 = *(const float4*)(g_k + (size_t)s * HD + 4 * lane);
        float4 e4 = *(const float4*)(ep + 4 * el);
        float p = q4.x * k4.x + q4.y * k4.y + q4.z * k4.z + q4.w * k4.w
                + qp4.x * e4.x + qp4.y * e4.y + qp4.z * e4.z + qp4.w * e4.w;
        p += __shfl_xor_sync(0xffffffffu, p, 1);
        p += __shfl_xor_sync(0xffffffffu, p, 2);
        p += __shfl_xor_sync(0xffffffffu, p, 4);
        p += __shfl_xor_sync(0xffffffffu, p, 8);
        float a = p * 0.125f;
        if (el == 0) g_alpha[2 * (size_t)e + (lane >> 4)] = a;
        mx = fmaxf(mx, a);
    }
    if (lane == 0)  g_mmax[2 * i]     = mx;
    if (lane == 16) g_mmax[2 * i + 1] = mx;
}

__global__ void k_attn1_v(const float* __restrict__ edge_attr) {
    __shared__ float smx[16];
    int i = NN + blockIdx.x;
    int tid = threadIdx.x, lane = tid & 31, wid = tid >> 5;
    int el = lane & 15;
    float4 q4  = *(const float4*)(g_q  + (size_t)i * HD + 4 * lane);
    float4 qp4 = *(const float4*)(g_qp + (size_t)i * HD + 4 * lane);
    int e0 = g_rowptr[i], e1 = g_rowptr[i + 1];
    float mx = -INFINITY;
    for (int e = e0 + wid; e < e1; e += 8) {
        int s = g_esrc[e], m = g_eid[e];
        const float* ep = (m < EE) ? edge_attr + (size_t)m * D64
                                   : g_tail + (size_t)(m - EE) * D64;
        float4 k4 = *(const float4*)(g_k + (size_t)s * HD + 4 * lane);
        float4 e4 = *(const float4*)(ep + 4 * el);
        float p = q4.x * k4.x + q4.y * k4.y + q4.z * k4.z + q4.w * k4.w
                + qp4.x * e4.x + qp4.y * e4.y + qp4.z * e4.z + qp4.w * e4.w;
        p += __shfl_xor_sync(0xffffffffu, p, 1);
        p += __shfl_xor_sync(0xffffffffu, p, 2);
        p += __shfl_xor_sync(0xffffffffu, p, 4);
        p += __shfl_xor_sync(0xffffffffu, p, 8);
        float a = p * 0.125f;
        if (el == 0) g_alpha[2 * (size_t)e + (lane >> 4)] = a;
        mx = fmaxf(mx, a);
    }
    if (el == 0) smx[wid * 2 + (lane >> 4)] = mx;
    __syncthreads();
    if (tid < 2) {
        float m = -INFINITY;
#pragma unroll
        for (int w = 0; w < 8; w++) m = fmaxf(m, smx[w * 2 + tid]);
        g_mmax[2 * i + tid] = m;
    }
}

// ---------------- attention pass 2: exp-weighted accumulate (no shuffles) ----------------
__global__ void k_attn2(const float* __restrict__ edge_attr) {
    int i = (blockIdx.x * blockDim.x + threadIdx.x) >> 5;
    int lane = threadIdx.x & 31;
    if (i >= NN) return;
    int el = lane & 15;
    int hh = lane >> 4;
    float mx = g_mmax[2 * i + hh];
    int e0 = g_rowptr[i], e1 = g_rowptr[i + 1];
    float sum = 0.f;
    float4 vacc = {0.f, 0.f, 0.f, 0.f};
    float4 eacc = {0.f, 0.f, 0.f, 0.f};
    for (int e = e0; e < e1; e++) {
        int s = g_esrc[e], m = g_eid[e];
        const float* ep = (m < EE) ? edge_attr + (size_t)m * D64
                                   : g_tail + (size_t)(m - EE) * D64;
        float w = expf(g_alpha[2 * (size_t)e + hh] - mx);
        sum += w;
        float4 v4 = *(const float4*)(g_v + (size_t)s * HD + 4 * lane);
        float4 e4 = *(const float4*)(ep + 4 * el);
        vacc.x += w * v4.x; vacc.y += w * v4.y; vacc.z += w * v4.z; vacc.w += w * v4.w;
        eacc.x += w * e4.x; eacc.y += w * e4.y; eacc.z += w * e4.z; eacc.w += w * e4.w;
    }
    float inv = 1.f / (sum + 1e-16f);
    float4 to = {vacc.x * inv, vacc.y * inv, vacc.z * inv, vacc.w * inv};
    float4 wo = {eacc.x * inv, eacc.y * inv, eacc.z * inv, eacc.w * inv};
    *(float4*)(g_t  + (size_t)i * HD + 4 * lane) = to;
    *(float4*)(g_we + (size_t)i * HD + 4 * lane) = wo;
}

__global__ void k_attn2_v(const float* __restrict__ edge_attr) {
    __shared__ float sv[128];
    __shared__ float se[128];
    __shared__ float ss[2];
    int i = NN + blockIdx.x;
    int tid = threadIdx.x, lane = tid & 31, wid = tid >> 5;
    int el = lane & 15;
    int hh = lane >> 4;
    if (tid < 128) { sv[tid] = 0.f; se[tid] = 0.f; }
    if (tid < 2) ss[tid] = 0.f;
    __syncthreads();
    float mx = g_mmax[2 * i + hh];
    int e0 = g_rowptr[i], e1 = g_rowptr[i + 1];
    float sum = 0.f;
    float4 vacc = {0.f, 0.f, 0.f, 0.f};
    float4 eacc = {0.f, 0.f, 0.f, 0.f};
    for (int e = e0 + wid; e < e1; e += 8) {
        int s = g_esrc[e], m = g_eid[e];
        const float* ep = (m < EE) ? edge_attr + (size_t)m * D64
                                   : g_tail + (size_t)(m - EE) * D64;
        float w = expf(g_alpha[2 * (size_t)e + hh] - mx);
        sum += w;
        float4 v4 = *(const float4*)(g_v + (size_t)s * HD + 4 * lane);
        float4 e4 = *(const float4*)(ep + 4 * el);
        vacc.x += w * v4.x; vacc.y += w * v4.y; vacc.z += w * v4.z; vacc.w += w * v4.w;
        eacc.x += w * e4.x; eacc.y += w * e4.y; eacc.z += w * e4.z; eacc.w += w * e4.w;
    }
    atomicAdd(&sv[4 * lane],     vacc.x); atomicAdd(&sv[4 * lane + 1], vacc.y);
    atomicAdd(&sv[4 * lane + 2], vacc.z); atomicAdd(&sv[4 * lane + 3], vacc.w);
    atomicAdd(&se[4 * lane],     eacc.x); atomicAdd(&se[4 * lane + 1], eacc.y);
    atomicAdd(&se[4 * lane + 2], eacc.z); atomicAdd(&se[4 * lane + 3], eacc.w);
    if (el == 0) atomicAdd(&ss[hh], sum);
    __syncthreads();
    if (tid < 128) {
        float inv = 1.f / (ss[tid >> 6] + 1e-16f);
        g_t [(size_t)i * HD + tid] = sv[tid] * inv;
        g_we[(size_t)i * HD + tid] = se[tid] * inv;
    }
}

// ---------------- block-diagonal weight builders ----------------
__global__ void k_build_w2(const float* __restrict__ ew) {
    int idx = blockIdx.x * blockDim.x + threadIdx.x;
    if (idx >= HD * HD) return;
    int r = idx >> 7, o = idx & 127;
    int h = r >> 6, d = r & 63, h2 = o >> 6, c = o & 63;
    g_w2[idx] = (h == h2) ? ew[(size_t)c * HD + h * 64 + d] : 0.f;
}
__global__ void k_build_w3(const float* __restrict__ ew) {
    int idx = blockIdx.x * blockDim.x + threadIdx.x;
    if (idx >= HD * HD) return;
    int r = idx >> 7, o = idx & 127;
    int h = r >> 6, c = r & 63, h2 = o >> 6, o2 = o & 63;
    g_w3[idx] = (h == h2) ? ew[(size_t)c * HD + h2 * 64 + o2] : 0.f;
}

// fused lin bias: blb = lb + sb @ lw
__global__ void k_biaslin(const float* __restrict__ sb, const float* __restrict__ lw,
                          const float* __restrict__ lb) {
    int o = threadIdx.x;
    if (o >= D64) return;
    float acc = lb[o];
    for (int k2 = 0; k2 < HD; k2++) acc += sb[k2] * lw[(size_t)k2 * D64 + o];
    g_blb[o] = acc;
}

// ---------------- GEMM: 128-row x OUTT-col tile, 8x(OUTT/16) per thread ----------------
template <int IN, int OUTT, int ACT, int ACCUM>
__global__ __launch_bounds__(256) void k_gemm2(
        const float* __restrict__ A, const float* __restrict__ W,
        const float* __restrict__ bias, float* __restrict__ C,
        int ldc, int rows, int wld) {
    __shared__ float As[32][132];
    __shared__ float Ws[32][OUTT];
    constexpr int CT = OUTT / 16;
    const int tid = threadIdx.x;
    const int tx = tid & 15;
    const int ty = tid >> 4;
    const int r0 = blockIdx.x * 128;
    const int col0 = blockIdx.y * OUTT;
    float acc[8][CT];
#pragma unroll
    for (int i = 0; i < 8; i++)
#pragma unroll
        for (int j = 0; j < CT; j++) acc[i][j] = 0.f;

    for (int k0 = 0; k0 < IN; k0 += 32) {
        // A tile (transposed into As[k][row])
#pragma unroll
        for (int t = 0; t < 4; t++) {
            int li = tid + t * 256;
            int r = li >> 3, kq = li & 7;
            int row = r0 + r;
            float4 av = make_float4(0.f, 0.f, 0.f, 0.f);
            if (row < rows) av = *(const float4*)(A + (size_t)row * IN + k0 + kq * 4);
            As[kq * 4 + 0][r] = av.x;
            As[kq * 4 + 1][r] = av.y;
            As[kq * 4 + 2][r] = av.z;
            As[kq * 4 + 3][r] = av.w;
        }
        // W tile
#pragma unroll
        for (int t = 0; t < OUTT / 32; t++) {
            int li = tid + t * 256;
            int kk = li / (OUTT / 4), oq = li % (OUTT / 4);
            ((float4*)(&Ws[kk][0]))[oq] =
                *(const float4*)(W + (size_t)(k0 + kk) * wld + col0 + oq * 4);
        }
        __syncthreads();
#pragma unroll
        for (int kk = 0; kk < 32; kk++) {
            float4 a0 = *(const float4*)&As[kk][ty * 8];
            float4 a1 = *(const float4*)&As[kk][ty * 8 + 4];
            float av[8] = {a0.x, a0.y, a0.z, a0.w, a1.x, a1.y, a1.z, a1.w};
            float wv[CT];
            float4 w0 = *(const float4*)&Ws[kk][tx * CT];
            wv[0] = w0.x; wv[1] = w0.y; wv[2] = w0.z; wv[3] = w0.w;
            if (CT == 8) {
                float4 w1 = *(const float4*)&Ws[kk][tx * CT + 4];
                wv[4] = w1.x; wv[5] = w1.y; wv[6] = w1.z; wv[7] = w1.w;
            }
#pragma unroll
            for (int i = 0; i < 8; i++)
#pragma unroll
                for (int j = 0; j < CT; j++) acc[i][j] += av[i] * wv[j];
        }
        __syncthreads();
    }
#pragma unroll
    for (int i = 0; i < 8; i++) {
        int row = r0 + ty * 8 + i;
        if (row >= rows) continue;
#pragma unroll
        for (int j = 0; j < CT; j++) {
            int col = col0 + tx * CT + j;
            float v = acc[i][j] + (bias ? bias[col] : 0.f);
            if (ACT == 1) v = (v > 0.f) ? v : 0.01f * v;
            float* cp = &C[(size_t)row * ldc + col];
            if (ACCUM) *cp += v; else *cp = v;
        }
    }
}

// ---------------- outputs ----------------
__global__ void k_glob_sum(const int* __restrict__ batch) {
    int idx = blockIdx.x * blockDim.x + threadIdx.x;
    if (idx >= NN * D64) return;
    atomicAdd(&g_gsum[batch[idx >> 6] * D64 + (idx & 63)], g_h[idx]);
}

__global__ void k_glob_out(float* __restrict__ out) {
    int idx = blockIdx.x * blockDim.x + threadIdx.x;
    if (idx >= GG * D64) return;
    int g = idx >> 6;
    out[NN * D64 + idx] = g_gsum[idx] / fmaxf(g_cntn[g], 1.f) + g_h[NN * D64 + idx];
}

__global__ void k_ne_out(const int* __restrict__ ne0, const int* __restrict__ ne1,
                         float* __restrict__ out) {
    int idx = blockIdx.x * blockDim.x + threadIdx.x;
    if (idx >= NE_ * D64) return;
    int j = idx >> 6, d = idx & 63;
    out[(NN + GG) * D64 + idx] = g_h[ne0[j] * D64 + d] + g_h[ne1[j] * D64 + d];
}

__global__ void k_cleanup() {
    int idx = blockIdx.x * blockDim.x + threadIdx.x;
    if (idx < GG * D64) g_gsum[idx] = 0.f;
    if (idx < GG) g_cntn[idx] = 0.f;
}

// ---------------- host launcher ----------------
#define GETSYM(ptr, sym) do { void* _p; cudaGetSymbolAddress(&_p, sym); ptr = (decltype(ptr))_p; } while (0)

extern "C" void kernel_launch(void* const* d_in, const int* in_sizes, int n_in,
                              void* d_out, int out_size) {
    const float* x          = (const float*)d_in[0];
    const float* cond       = (const float*)d_in[1];
    const float* edge_attr  = (const float*)d_in[2];
    const int*   edge_index = (const int*)d_in[3];
    const int*   ne_index   = (const int*)d_in[4];
    const int*   batch      = (const int*)d_in[5];
    const float* gen_w  = (const float*)d_in[6];
    const float* gen_b  = (const float*)d_in[7];
    const float* q_w    = (const float*)d_in[8];
    const float* q_b    = (const float*)d_in[9];
    const float* k_w    = (const float*)d_in[10];
    const float* k_b    = (const float*)d_in[11];
    const float* v_w    = (const float*)d_in[12];
    const float* v_b    = (const float*)d_in[13];
    const float* e_w    = (const float*)d_in[14];
    const float* skip_w = (const float*)d_in[15];
    const float* skip_b = (const float*)d_in[16];
    const float* lin_w  = (const float*)d_in[17];
    const float* lin_b  = (const float*)d_in[18];
    const float* ff_w1  = (const float*)d_in[19];
    const float* ff_b1  = (const float*)d_in[20];
    const float* ff_w2  = (const float*)d_in[21];
    const float* ff_b2  = (const float*)d_in[22];
    float* out = (float*)d_out;

    float *h_p, *hn_p, *agg_p, *cat_p, *q_p, *k_p, *v_p, *qp_p, *t_p, *we_p;
    float *lh_p, *ln2_p, *ffh_p, *w2_p, *w3_p, *swlw_p, *lw3_p, *blb_p;
    GETSYM(h_p, g_h);     GETSYM(hn_p, g_hn);   GETSYM(agg_p, g_agg);
    GETSYM(cat_p, g_cat); GETSYM(q_p, g_q);     GETSYM(k_p, g_k);
    GETSYM(v_p, g_v);     GETSYM(qp_p, g_qp);   GETSYM(t_p, g_t);
    GETSYM(we_p, g_we);   GETSYM(lh_p, g_lh);   GETSYM(ln2_p, g_ln2);
    GETSYM(ffh_p, g_ffh); GETSYM(w2_p, g_w2);   GETSYM(w3_p, g_w3);
    GETSYM(swlw_p, g_swlw); GETSYM(lw3_p, g_lw3); GETSYM(blb_p, g_blb);

    const int T = 256;
    const int GRID_N = CDIV(NAUG, 128);
    cudaStream_t st = 0;

    // ---- setup: CSR build + aux (all state is self-cleaning across launches) ----
    k_build_edges<<<CDIV(MM, T), T, 0, st>>>(edge_index, edge_index + EE, batch);
    k_scanA<<<NB_SCAN, 256, 0, st>>>();
    k_scanB<<<1, 256, 0, st>>>();
    k_scanC<<<NB_SCAN, 256, 0, st>>>();
    k_scatter<<<CDIV(MM, T), T, 0, st>>>();
    k_abatch<<<CDIV(NAUG, T), T, 0, st>>>(batch);
    k_cntn<<<CDIV(NN, T), T, 0, st>>>(batch);
    k_init_h<<<CDIV(NAUG * D64, T), T, 0, st>>>(x, cond);
    k_tail_ep<<<CDIV(2 * NN * D64, T), T, 0, st>>>();
    k_tail_csr<<<CDIV(NAUG * 32, T), T, 0, st>>>(edge_attr);

    // ---- layers ----
    for (int i = 0; i < LL; i++) {
        const float* gw  = gen_w  + (size_t)i * D64 * D64;
        const float* gb  = gen_b  + (size_t)i * D64;
        const float* qw  = q_w    + (size_t)i * HD * HD;
        const float* qb  = q_b    + (size_t)i * HD;
        const float* kw  = k_w    + (size_t)i * HD * HD;
        const float* kb  = k_b    + (size_t)i * HD;
        const float* vw  = v_w    + (size_t)i * HD * HD;
        const float* vb  = v_b    + (size_t)i * HD;
        const float* ew  = e_w    + (size_t)i * D64 * HD;
        const float* sw  = skip_w + (size_t)i * HD * HD;
        const float* sb  = skip_b + (size_t)i * HD;
        const float* lw  = lin_w  + (size_t)i * HD * D64;
        const float* lb  = lin_b  + (size_t)i * D64;
        const float* f1w = ff_w1  + (size_t)i * D64 * 4 * D64;
        const float* f1b = ff_b1  + (size_t)i * 4 * D64;
        const float* f2w = ff_w2  + (size_t)i * 4 * D64 * D64;
        const float* f2b = ff_b2  + (size_t)i * D64;

        // weight precomputes (independent of node data)
        k_build_w2<<<CDIV(HD * HD, T), T, 0, st>>>(ew);
        k_build_w3<<<CDIV(HD * HD, T), T, 0, st>>>(ew);
        k_gemm2<HD, D64, 0, 0><<<dim3(1, 1), T, 0, st>>>(sw, lw, nullptr, swlw_p, D64, HD, D64);
        k_gemm2<HD, D64, 0, 0><<<dim3(1, 1), T, 0, st>>>(w3_p, lw, nullptr, lw3_p, D64, HD, D64);
        k_biaslin<<<1, 64, 0, st>>>(sb, lw, lb);

        // LN1 -> hn + cat left half
        k_ln_stats<<<CDIV(NAUG * 32, T), T, 0, st>>>(h_p);
        k_ln_final<<<1, GG, 0, st>>>();
        k_ln_apply2<<<CDIV(NAUG * D64, T), T, 0, st>>>(h_p);

        // gen_conv -> agg ; gemm -> cat right half
        k_gen<<<CDIV(NN * 32, T), T, 0, st>>>(edge_attr);
        k_gen_v<<<GG, T, 0, st>>>(edge_attr);
        k_gemm2<D64, D64, 0, 0><<<dim3(GRID_N, 1), T, 0, st>>>(agg_p, gw, gb, cat_p + D64, HD, NAUG, D64);

        // q, k, v, qp
        k_gemm2<HD, HD, 0, 0><<<dim3(GRID_N, 1), T, 0, st>>>(cat_p, qw, qb, q_p, HD, NAUG, HD);
        k_gemm2<HD, HD, 0, 0><<<dim3(GRID_N, 1), T, 0, st>>>(cat_p, kw, kb, k_p, HD, NAUG, HD);
        k_gemm2<HD, HD, 0, 0><<<dim3(GRID_N, 1), T, 0, st>>>(cat_p, vw, vb, v_p, HD, NAUG, HD);
        k_gemm2<HD, HD, 0, 0><<<dim3(GRID_N, 1), T, 0, st>>>(q_p, w2_p, nullptr, qp_p, HD, NAUG, HD);

        // attention
        k_attn1<<<CDIV(NN * 32, T), T, 0, st>>>(edge_attr);
        k_attn1_v<<<GG, T, 0, st>>>(edge_attr);
        k_attn2<<<CDIV(NN * 32, T), T, 0, st>>>(edge_attr);
        k_attn2_v<<<GG, T, 0, st>>>(edge_attr);

        // lh = t@lw + blb + cat@swlw + we@lw3
        k_gemm2<HD, D64, 0, 0><<<dim3(GRID_N, 1), T, 0, st>>>(t_p, lw, blb_p, lh_p, D64, NAUG, D64);
        k_gemm2<HD, D64, 0, 1><<<dim3(GRID_N, 1), T, 0, st>>>(cat_p, swlw_p, nullptr, lh_p, D64, NAUG, D64);
        k_gemm2<HD, D64, 0, 1><<<dim3(GRID_N, 1), T, 0, st>>>(we_p, lw3_p, nullptr, lh_p, D64, NAUG, D64);

        // LN2
        k_ln_stats<<<CDIV(NAUG * 32, T), T, 0, st>>>(lh_p);
        k_ln_final<<<1, GG, 0, st>>>();
        k_ln_apply<<<CDIV(NAUG * D64, T), T, 0, st>>>(lh_p, ln2_p);

        // FF + residual
        k_gemm2<D64, HD, 1, 0><<<dim3(GRID_N, 2), T, 0, st>>>(ln2_p, f1w, f1b, ffh_p, 4 * D64, NAUG, 4 * D64);
        k_gemm2<4 * D64, D64, 0, 1><<<dim3(GRID_N, 1), T, 0, st>>>(ffh_p, f2w, f2b, h_p, D64, NAUG, D64);
    }

    // ---- outputs ----
    cudaMemcpyAsync(out, h_p, sizeof(float) * NN * D64, cudaMemcpyDeviceToDevice, st);
    k_glob_sum<<<CDIV(NN * D64, T), T, 0, st>>>(batch);
    k_glob_out<<<CDIV(GG * D64, T), T, 0, st>>>(out);
    k_ne_out<<<CDIV(NE_ * D64, T), T, 0, st>>>(ne_index, ne_index + NE_, out);
    k_cleanup<<<CDIV(GG * D64, T), T, 0, st>>>();
}

// round 4
// speedup vs baseline: 1.8158x; 1.1287x over previous
#include <cuda_runtime.h>
#include <math.h>
#include <stdint.h>

// Problem constants
#define D64   64
#define HH    2
#define HD    128
#define LL    3
#define NN    50000
#define GG    128
#define EE    600000
#define NE_   300000
#define NAUG  (NN + GG)          // 50128
#define M0    (EE + 2 * NN)      // 700000
#define MM    (M0 + NAUG)        // 750128
#define TAILR (MM - EE)          // 150128
#define NB_SCAN ((NAUG + 255) / 256)   // 196

#define CDIV(a, b) (((a) + (b) - 1) / (b))

// ---------------- device scratch (static, no allocs) ----------------
__device__ int    g_src[MM];
__device__ int    g_dst[MM];
__device__ int    g_deg[NAUG];
__device__ int    g_rowptr[NAUG + 1];
__device__ int    g_bsum[256];
__device__ int    g_fill[NAUG];
__device__ int    g_esrc[MM];
__device__ int    g_eid[MM];
__device__ float  g_alpha[(size_t)MM * HH];
__device__ float  g_tail[(size_t)TAILR * D64];   // e_aug rows >= EE
__device__ float  g_h[NAUG * D64];
__device__ float  g_hn[NAUG * D64];
__device__ float  g_agg[NAUG * D64];
__device__ float  g_big[(size_t)NAUG * 384];     // [cat(128) | t(128) | we(128)]
__device__ float  g_qkvp[(size_t)NAUG * 512];    // [q | k | v | qp]
__device__ float  g_lh[NAUG * D64];
__device__ float  g_ln2[NAUG * D64];
__device__ float  g_ffh[(size_t)NAUG * 256];
__device__ float  g_w2[HD * HD];
__device__ float  g_w3[HD * HD];
__device__ float  g_qpw[HD * HD];
__device__ float  g_swlw[HD * D64];
__device__ float  g_lw3[HD * D64];
__device__ float  g_wcat[HD * 512];
__device__ float  g_bcat[512];
__device__ float  g_wlin[384 * D64];
__device__ float  g_blb[D64];
__device__ float  g_mmax[NAUG * HH];
__device__ float  g_cntn[GG];
__device__ double g_lsum[GG];
__device__ double g_lsumsq[GG];
__device__ float  g_mean[GG];
__device__ float  g_rstd[GG];
__device__ int    g_abatch[NAUG];
__device__ float  g_gsum[GG * D64];

// ---------------- setup kernels ----------------
__global__ void k_build_edges(const int* __restrict__ ei0, const int* __restrict__ ei1,
                              const int* __restrict__ batch) {
    int m = blockIdx.x * blockDim.x + threadIdx.x;
    if (m >= MM) return;
    int s, d;
    if (m < EE)               { s = ei0[m]; d = ei1[m]; }
    else if (m < EE + NN)     { int i = m - EE;          s = i;             d = batch[i] + NN; }
    else if (m < EE + 2 * NN) { int i = m - EE - NN;     s = batch[i] + NN; d = i; }
    else                      { int i = m - EE - 2 * NN; s = i;             d = i; }
    g_src[m] = s; g_dst[m] = d;
    atomicAdd(&g_deg[d], 1);
}

__global__ void k_scanA() {
    __shared__ int sh[256];
    int t = threadIdx.x;
    int i = blockIdx.x * 256 + t;
    int v = (i < NAUG) ? g_deg[i] : 0;
    sh[t] = v;
    __syncthreads();
    for (int off = 1; off < 256; off <<= 1) {
        int a = (t >= off) ? sh[t - off] : 0;
        __syncthreads();
        sh[t] += a;
        __syncthreads();
    }
    if (i < NAUG) g_rowptr[i] = sh[t] - v;
    if (t == 255) g_bsum[blockIdx.x] = sh[255];
}

__global__ void k_scanB() {
    __shared__ int sh[256];
    int t = threadIdx.x;
    int v = (t < NB_SCAN) ? g_bsum[t] : 0;
    sh[t] = v;
    __syncthreads();
    for (int off = 1; off < 256; off <<= 1) {
        int a = (t >= off) ? sh[t - off] : 0;
        __syncthreads();
        sh[t] += a;
        __syncthreads();
    }
    if (t < NB_SCAN) g_bsum[t] = sh[t] - v;
}

__global__ void k_scanC() {
    int i = blockIdx.x * 256 + threadIdx.x;
    if (i < NAUG) {
        int r = g_rowptr[i] + g_bsum[i >> 8];
        g_rowptr[i] = r;
        g_fill[i] = r;
        g_deg[i] = 0;                 // self-clean
    }
    if (i == 0) g_rowptr[NAUG] = MM;
}

__global__ void k_scatter() {
    int m = blockIdx.x * blockDim.x + threadIdx.x;
    if (m >= MM) return;
    int pos = atomicAdd(&g_fill[g_dst[m]], 1);
    g_esrc[pos] = g_src[m];
    g_eid[pos]  = m;
}

__global__ void k_abatch(const int* __restrict__ batch) {
    int i = blockIdx.x * blockDim.x + threadIdx.x;
    if (i >= NAUG) return;
    g_abatch[i] = (i < NN) ? batch[i] : (i - NN);
}

__global__ void k_cntn(const int* __restrict__ batch) {
    int i = blockIdx.x * blockDim.x + threadIdx.x;
    if (i >= NN) return;
    atomicAdd(&g_cntn[batch[i]], 1.f);
}

__global__ void k_init_h(const float* __restrict__ x, const float* __restrict__ cond) {
    int idx = blockIdx.x * blockDim.x + threadIdx.x;
    if (idx >= NAUG * D64) return;
    g_h[idx] = (idx < NN * D64) ? x[idx] : cond[idx - NN * D64];
}

__global__ void k_tail_ep() {
    int idx = blockIdx.x * blockDim.x + threadIdx.x;
    if (idx >= 2 * NN * D64) return;
    g_tail[idx] = ((idx & 63) == 0) ? 1.f : 0.f;
}

__global__ void k_tail_csr(const float* __restrict__ edge_attr) {
    int i = (blockIdx.x * blockDim.x + threadIdx.x) >> 5;
    int lane = threadIdx.x & 31;
    if (i >= NAUG) return;
    float2 acc = {0.f, 0.f};
    float cnt = 0.f;
    int e0 = g_rowptr[i], e1 = g_rowptr[i + 1];
    for (int e = e0; e < e1; e++) {
        int m = g_eid[e];
        if (m < EE) {
            float2 ev = ((const float2*)(edge_attr + (size_t)m * D64))[lane];
            acc.x += ev.x; acc.y += ev.y;
            cnt += 1.f;
        } else if (m < M0) {
            if (lane == 0) acc.x += 1.f;
            cnt += 1.f;
        }
    }
    float invc = 1.f / fmaxf(cnt, 1.f);
    float2 o = {acc.x * invc, acc.y * invc};
    ((float2*)(g_tail + (size_t)(2 * NN + i) * D64))[lane] = o;
}

// ---------------- graph layernorm ----------------
__global__ void k_ln_stats(const float* __restrict__ X) {
    int i = (blockIdx.x * blockDim.x + threadIdx.x) >> 5;
    int lane = threadIdx.x & 31;
    if (i >= NAUG) return;
    float2 v = ((const float2*)(X + (size_t)i * D64))[lane];
    float s  = v.x + v.y;
    float ss = v.x * v.x + v.y * v.y;
#pragma unroll
    for (int off = 16; off; off >>= 1) {
        s  += __shfl_xor_sync(0xffffffffu, s, off);
        ss += __shfl_xor_sync(0xffffffffu, ss, off);
    }
    if (lane == 0) {
        int b = g_abatch[i];
        atomicAdd(&g_lsum[b], (double)s);
        atomicAdd(&g_lsumsq[b], (double)ss);
    }
}

__global__ void k_ln_final() {
    int g = threadIdx.x;
    if (g >= GG) return;
    double norm = (double)fmaxf(g_cntn[g] + 1.f, 1.f) * D64;
    double mean = g_lsum[g] / norm;
    double var  = g_lsumsq[g] / norm - mean * mean;
    g_mean[g] = (float)mean;
    g_rstd[g] = rsqrtf((float)var + 1e-5f);
    g_lsum[g] = 0.0;            // self-clean
    g_lsumsq[g] = 0.0;
}

// writes hn AND big[:, 0:64] (cat left half)
__global__ void k_ln_apply2(const float* __restrict__ X) {
    int idx = blockIdx.x * blockDim.x + threadIdx.x;
    if (idx >= NAUG * D64) return;
    int i = idx >> 6, d = idx & 63;
    int b = g_abatch[i];
    float v = (X[idx] - g_mean[b]) * g_rstd[b];
    g_hn[idx] = v;
    g_big[(size_t)i * 384 + d] = v;
}

__global__ void k_ln_apply(const float* __restrict__ X, float* __restrict__ Y) {
    int idx = blockIdx.x * blockDim.x + threadIdx.x;
    if (idx >= NAUG * D64) return;
    int b = g_abatch[idx >> 6];
    Y[idx] = (X[idx] - g_mean[b]) * g_rstd[b];
}

// ---------------- gen_conv: regular nodes (warp each) ----------------
__global__ void k_gen(const float* __restrict__ edge_attr) {
    int i = (blockIdx.x * blockDim.x + threadIdx.x) >> 5;
    int lane = threadIdx.x & 31;
    if (i >= NN) return;
    float2 acc = {0.f, 0.f};
    int e0 = g_rowptr[i], e1 = g_rowptr[i + 1];
    for (int e = e0; e < e1; e++) {
        int s = g_esrc[e], m = g_eid[e];
        const float* ep = (m < EE) ? edge_attr + (size_t)m * D64
                                   : g_tail + (size_t)(m - EE) * D64;
        float2 ev = ((const float2*)ep)[lane];
        float2 hv = ((const float2*)(g_hn + (size_t)s * D64))[lane];
        acc.x += fmaxf(hv.x + ev.x, 0.f) + 1e-7f;
        acc.y += fmaxf(hv.y + ev.y, 0.f) + 1e-7f;
    }
    float2 hi = ((const float2*)(g_hn + (size_t)i * D64))[lane];
    float2 o = {acc.x + hi.x, acc.y + hi.y};
    ((float2*)(g_agg + (size_t)i * D64))[lane] = o;
}

__global__ void k_gen_v(const float* __restrict__ edge_attr) {
    __shared__ float sa[64];
    int i = NN + blockIdx.x;
    int tid = threadIdx.x, lane = tid & 31, wid = tid >> 5;
    if (tid < 64) sa[tid] = 0.f;
    __syncthreads();
    int e0 = g_rowptr[i], e1 = g_rowptr[i + 1];
    float2 acc = {0.f, 0.f};
    for (int e = e0 + wid; e < e1; e += 8) {
        int s = g_esrc[e], m = g_eid[e];
        const float* ep = (m < EE) ? edge_attr + (size_t)m * D64
                                   : g_tail + (size_t)(m - EE) * D64;
        float2 ev = ((const float2*)ep)[lane];
        float2 hv = ((const float2*)(g_hn + (size_t)s * D64))[lane];
        acc.x += fmaxf(hv.x + ev.x, 0.f) + 1e-7f;
        acc.y += fmaxf(hv.y + ev.y, 0.f) + 1e-7f;
    }
    atomicAdd(&sa[2 * lane],     acc.x);
    atomicAdd(&sa[2 * lane + 1], acc.y);
    __syncthreads();
    if (tid < 64) g_agg[(size_t)i * D64 + tid] = sa[tid] + g_hn[(size_t)i * D64 + tid];
}

// ---------------- attention pass 1: alpha + segment max ----------------
__global__ void k_attn1(const float* __restrict__ edge_attr) {
    int i = (blockIdx.x * blockDim.x + threadIdx.x) >> 5;
    int lane = threadIdx.x & 31;
    if (i >= NN) return;
    int el = lane & 15;
    float4 q4  = *(const float4*)(g_qkvp + (size_t)i * 512 + 4 * lane);
    float4 qp4 = *(const float4*)(g_qkvp + (size_t)i * 512 + 384 + 4 * lane);
    int e0 = g_rowptr[i], e1 = g_rowptr[i + 1];
    float mx = -INFINITY;
    for (int e = e0; e < e1; e++) {
        int s = g_esrc[e], m = g_eid[e];
        const float* ep = (m < EE) ? edge_attr + (size_t)m * D64
                                   : g_tail + (size_t)(m - EE) * D64;
        float4 k4 = *(const float4*)(g_qkvp + (size_t)s * 512 + 128 + 4 * lane);
        float4 e4 = *(const float4*)(ep + 4 * el);
        float p = q4.x * k4.x + q4.y * k4.y + q4.z * k4.z + q4.w * k4.w
                + qp4.x * e4.x + qp4.y * e4.y + qp4.z * e4.z + qp4.w * e4.w;
        p += __shfl_xor_sync(0xffffffffu, p, 1);
        p += __shfl_xor_sync(0xffffffffu, p, 2);
        p += __shfl_xor_sync(0xffffffffu, p, 4);
        p += __shfl_xor_sync(0xffffffffu, p, 8);
        float a = p * 0.125f;
        if (el == 0) g_alpha[2 * (size_t)e + (lane >> 4)] = a;
        mx = fmaxf(mx, a);
    }
    if (lane == 0)  g_mmax[2 * i]     = mx;
    if (lane == 16) g_mmax[2 * i + 1] = mx;
}

__global__ void k_attn1_v(const float* __restrict__ edge_attr) {
    __shared__ float smx[16];
    int i = NN + blockIdx.x;
    int tid = threadIdx.x, lane = tid & 31, wid = tid >> 5;
    int el = lane & 15;
    float4 q4  = *(const float4*)(g_qkvp + (size_t)i * 512 + 4 * lane);
    float4 qp4 = *(const float4*)(g_qkvp + (size_t)i * 512 + 384 + 4 * lane);
    int e0 = g_rowptr[i], e1 = g_rowptr[i + 1];
    float mx = -INFINITY;
    for (int e = e0 + wid; e < e1; e += 8) {
        int s = g_esrc[e], m = g_eid[e];
        const float* ep = (m < EE) ? edge_attr + (size_t)m * D64
                                   : g_tail + (size_t)(m - EE) * D64;
        float4 k4 = *(const float4*)(g_qkvp + (size_t)s * 512 + 128 + 4 * lane);
        float4 e4 = *(const float4*)(ep + 4 * el);
        float p = q4.x * k4.x + q4.y * k4.y + q4.z * k4.z + q4.w * k4.w
                + qp4.x * e4.x + qp4.y * e4.y + qp4.z * e4.z + qp4.w * e4.w;
        p += __shfl_xor_sync(0xffffffffu, p, 1);
        p += __shfl_xor_sync(0xffffffffu, p, 2);
        p += __shfl_xor_sync(0xffffffffu, p, 4);
        p += __shfl_xor_sync(0xffffffffu, p, 8);
        float a = p * 0.125f;
        if (el == 0) g_alpha[2 * (size_t)e + (lane >> 4)] = a;
        mx = fmaxf(mx, a);
    }
    if (el == 0) smx[wid * 2 + (lane >> 4)] = mx;
    __syncthreads();
    if (tid < 2) {
        float m = -INFINITY;
#pragma unroll
        for (int w = 0; w < 8; w++) m = fmaxf(m, smx[w * 2 + tid]);
        g_mmax[2 * i + tid] = m;
    }
}

// ---------------- attention pass 2: exp-weighted accumulate ----------------
__global__ void k_attn2(const float* __restrict__ edge_attr) {
    int i = (blockIdx.x * blockDim.x + threadIdx.x) >> 5;
    int lane = threadIdx.x & 31;
    if (i >= NN) return;
    int el = lane & 15;
    int hh = lane >> 4;
    float mx = g_mmax[2 * i + hh];
    int e0 = g_rowptr[i], e1 = g_rowptr[i + 1];
    float sum = 0.f;
    float4 vacc = {0.f, 0.f, 0.f, 0.f};
    float4 eacc = {0.f, 0.f, 0.f, 0.f};
    for (int e = e0; e < e1; e++) {
        int s = g_esrc[e], m = g_eid[e];
        const float* ep = (m < EE) ? edge_attr + (size_t)m * D64
                                   : g_tail + (size_t)(m - EE) * D64;
        float w = expf(g_alpha[2 * (size_t)e + hh] - mx);
        sum += w;
        float4 v4 = *(const float4*)(g_qkvp + (size_t)s * 512 + 256 + 4 * lane);
        float4 e4 = *(const float4*)(ep + 4 * el);
        vacc.x += w * v4.x; vacc.y += w * v4.y; vacc.z += w * v4.z; vacc.w += w * v4.w;
        eacc.x += w * e4.x; eacc.y += w * e4.y; eacc.z += w * e4.z; eacc.w += w * e4.w;
    }
    float inv = 1.f / (sum + 1e-16f);
    float4 to = {vacc.x * inv, vacc.y * inv, vacc.z * inv, vacc.w * inv};
    float4 wo = {eacc.x * inv, eacc.y * inv, eacc.z * inv, eacc.w * inv};
    *(float4*)(g_big + (size_t)i * 384 + 128 + 4 * lane) = to;
    *(float4*)(g_big + (size_t)i * 384 + 256 + 4 * lane) = wo;
}

__global__ void k_attn2_v(const float* __restrict__ edge_attr) {
    __shared__ float sv[128];
    __shared__ float se[128];
    __shared__ float ss[2];
    int i = NN + blockIdx.x;
    int tid = threadIdx.x, lane = tid & 31, wid = tid >> 5;
    int el = lane & 15;
    int hh = lane >> 4;
    if (tid < 128) { sv[tid] = 0.f; se[tid] = 0.f; }
    if (tid < 2) ss[tid] = 0.f;
    __syncthreads();
    float mx = g_mmax[2 * i + hh];
    int e0 = g_rowptr[i], e1 = g_rowptr[i + 1];
    float sum = 0.f;
    float4 vacc = {0.f, 0.f, 0.f, 0.f};
    float4 eacc = {0.f, 0.f, 0.f, 0.f};
    for (int e = e0 + wid; e < e1; e += 8) {
        int s = g_esrc[e], m = g_eid[e];
        const float* ep = (m < EE) ? edge_attr + (size_t)m * D64
                                   : g_tail + (size_t)(m - EE) * D64;
        float w = expf(g_alpha[2 * (size_t)e + hh] - mx);
        sum += w;
        float4 v4 = *(const float4*)(g_qkvp + (size_t)s * 512 + 256 + 4 * lane);
        float4 e4 = *(const float4*)(ep + 4 * el);
        vacc.x += w * v4.x; vacc.y += w * v4.y; vacc.z += w * v4.z; vacc.w += w * v4.w;
        eacc.x += w * e4.x; eacc.y += w * e4.y; eacc.z += w * e4.z; eacc.w += w * e4.w;
    }
    atomicAdd(&sv[4 * lane],     vacc.x); atomicAdd(&sv[4 * lane + 1], vacc.y);
    atomicAdd(&sv[4 * lane + 2], vacc.z); atomicAdd(&sv[4 * lane + 3], vacc.w);
    atomicAdd(&se[4 * lane],     eacc.x); atomicAdd(&se[4 * lane + 1], eacc.y);
    atomicAdd(&se[4 * lane + 2], eacc.z); atomicAdd(&se[4 * lane + 3], eacc.w);
    if (el == 0) atomicAdd(&ss[hh], sum);
    __syncthreads();
    if (tid < 128) {
        float inv = 1.f / (ss[tid >> 6] + 1e-16f);
        g_big[(size_t)i * 384 + 128 + tid] = sv[tid] * inv;
        g_big[(size_t)i * 384 + 256 + tid] = se[tid] * inv;
    }
}

// ---------------- block-diagonal weight builders ----------------
__global__ void k_build_w2(const float* __restrict__ ew) {
    int idx = blockIdx.x * blockDim.x + threadIdx.x;
    if (idx >= HD * HD) return;
    int r = idx >> 7, o = idx & 127;
    int h = r >> 6, d = r & 63, h2 = o >> 6, c = o & 63;
    g_w2[idx] = (h == h2) ? ew[(size_t)c * HD + h * 64 + d] : 0.f;
}
__global__ void k_build_w3(const float* __restrict__ ew) {
    int idx = blockIdx.x * blockDim.x + threadIdx.x;
    if (idx >= HD * HD) return;
    int r = idx >> 7, o = idx & 127;
    int h = r >> 6, c = r & 63, h2 = o >> 6, o2 = o & 63;
    g_w3[idx] = (h == h2) ? ew[(size_t)c * HD + h2 * 64 + o2] : 0.f;
}

__global__ void k_biaslin(const float* __restrict__ sb, const float* __restrict__ lw,
                          const float* __restrict__ lb) {
    int o = threadIdx.x;
    if (o >= D64) return;
    float acc = lb[o];
    for (int k2 = 0; k2 < HD; k2++) acc += sb[k2] * lw[(size_t)k2 * D64 + o];
    g_blb[o] = acc;
}

// wcat = [qw | kw | vw | qw@W2]  (128 x 512)
__global__ void k_wcat(const float* __restrict__ qw, const float* __restrict__ kw,
                       const float* __restrict__ vw) {
    int idx = blockIdx.x * blockDim.x + threadIdx.x;
    if (idx >= HD * 512) return;
    int r = idx >> 9, c = idx & 511;
    float v;
    if (c < 128)      v = qw[r * HD + c];
    else if (c < 256) v = kw[r * HD + c - 128];
    else if (c < 384) v = vw[r * HD + c - 256];
    else              v = g_qpw[r * HD + c - 384];
    g_wcat[idx] = v;
}

// bcat = [qb | kb | vb | qb@W2]
__global__ void k_bcat(const float* __restrict__ qb, const float* __restrict__ kb,
                       const float* __restrict__ vb) {
    int c = blockIdx.x * blockDim.x + threadIdx.x;
    if (c >= 512) return;
    float v;
    if (c < 128)      v = qb[c];
    else if (c < 256) v = kb[c - 128];
    else if (c < 384) v = vb[c - 256];
    else {
        int o = c - 384;
        float a = 0.f;
        for (int d = 0; d < HD; d++) a += qb[d] * g_w2[d * HD + o];
        v = a;
    }
    g_bcat[c] = v;
}

// wlin = [sw@lw ; lw ; W3@lw]  (384 x 64), matching big = [cat|t|we]
__global__ void k_wlin(const float* __restrict__ lw) {
    int idx = blockIdx.x * blockDim.x + threadIdx.x;
    if (idx >= 384 * D64) return;
    int r = idx >> 6, c = idx & 63;
    float v;
    if (r < 128)      v = g_swlw[r * D64 + c];
    else if (r < 256) v = lw[(size_t)(r - 128) * D64 + c];
    else              v = g_lw3[(r - 256) * D64 + c];
    g_wlin[idx] = v;
}

// ---------------- fp32 GEMM (weight prep only; rows ~128) ----------------
template <int IN, int OUTT, int ACT, int ACCUM>
__global__ __launch_bounds__(256) void k_gemm2(
        const float* __restrict__ A, const float* __restrict__ W,
        const float* __restrict__ bias, float* __restrict__ C,
        int ldc, int rows, int wld) {
    __shared__ float As[32][132];
    __shared__ float Ws[32][OUTT];
    constexpr int CT = OUTT / 16;
    const int tid = threadIdx.x;
    const int tx = tid & 15;
    const int ty = tid >> 4;
    const int r0 = blockIdx.x * 128;
    const int col0 = blockIdx.y * OUTT;
    float acc[8][CT];
#pragma unroll
    for (int i = 0; i < 8; i++)
#pragma unroll
        for (int j = 0; j < CT; j++) acc[i][j] = 0.f;

    for (int k0 = 0; k0 < IN; k0 += 32) {
#pragma unroll
        for (int t = 0; t < 4; t++) {
            int li = tid + t * 256;
            int r = li >> 3, kq = li & 7;
            int row = r0 + r;
            float4 av = make_float4(0.f, 0.f, 0.f, 0.f);
            if (row < rows) av = *(const float4*)(A + (size_t)row * IN + k0 + kq * 4);
            As[kq * 4 + 0][r] = av.x;
            As[kq * 4 + 1][r] = av.y;
            As[kq * 4 + 2][r] = av.z;
            As[kq * 4 + 3][r] = av.w;
        }
#pragma unroll
        for (int t = 0; t < OUTT / 32; t++) {
            int li = tid + t * 256;
            int kk = li / (OUTT / 4), oq = li % (OUTT / 4);
            ((float4*)(&Ws[kk][0]))[oq] =
                *(const float4*)(W + (size_t)(k0 + kk) * wld + col0 + oq * 4);
        }
        __syncthreads();
#pragma unroll
        for (int kk = 0; kk < 32; kk++) {
            float4 a0 = *(const float4*)&As[kk][ty * 8];
            float4 a1 = *(const float4*)&As[kk][ty * 8 + 4];
            float av[8] = {a0.x, a0.y, a0.z, a0.w, a1.x, a1.y, a1.z, a1.w};
            float wv[CT];
            float4 w0 = *(const float4*)&Ws[kk][tx * CT];
            wv[0] = w0.x; wv[1] = w0.y; wv[2] = w0.z; wv[3] = w0.w;
            if (CT == 8) {
                float4 w1 = *(const float4*)&Ws[kk][tx * CT + 4];
                wv[4] = w1.x; wv[5] = w1.y; wv[6] = w1.z; wv[7] = w1.w;
            }
#pragma unroll
            for (int i = 0; i < 8; i++)
#pragma unroll
                for (int j = 0; j < CT; j++) acc[i][j] += av[i] * wv[j];
        }
        __syncthreads();
    }
#pragma unroll
    for (int i = 0; i < 8; i++) {
        int row = r0 + ty * 8 + i;
        if (row >= rows) continue;
#pragma unroll
        for (int j = 0; j < CT; j++) {
            int col = col0 + tx * CT + j;
            float v = acc[i][j] + (bias ? bias[col] : 0.f);
            if (ACT == 1) v = (v > 0.f) ? v : 0.01f * v;
            float* cp = &C[(size_t)row * ldc + col];
            if (ACCUM) *cp += v; else *cp = v;
        }
    }
}

// ---------------- 3xTF32 tensor-core GEMM ----------------
__device__ __forceinline__ uint32_t f2tf(float f) {
    uint32_t u;
    asm("cvt.rna.tf32.f32 %0, %1;" : "=r"(u) : "f"(f));
    return u;
}

__device__ __forceinline__ void mma8(float* c, uint32_t a0, uint32_t a1, uint32_t a2,
                                     uint32_t a3, uint32_t b0, uint32_t b1) {
    asm volatile(
        "mma.sync.aligned.m16n8k8.row.col.f32.tf32.tf32.f32 "
        "{%0,%1,%2,%3}, {%4,%5,%6,%7}, {%8,%9}, {%0,%1,%2,%3};"
        : "+f"(c[0]), "+f"(c[1]), "+f"(c[2]), "+f"(c[3])
        : "r"(a0), "r"(a1), "r"(a2), "r"(a3), "r"(b0), "r"(b1));
}

// C[rows x OUT] = act(A[rows x K](lda) @ W[K x OUT](wld) + bias)
// block: 256 thr = 8 warps (4 m x 2 n), tile 128 x 64, K step 32.
template <int ACT, int ACCUM>
__global__ __launch_bounds__(256) void k_gemm_tc(
        const float* __restrict__ A, int lda,
        const float* __restrict__ W, int wld,
        const float* __restrict__ bias, float* __restrict__ C,
        int ldc, int rows, int K) {
    __shared__ __align__(16) float As[128][36];
    __shared__ __align__(16) float Ws[32][72];
    const int tid = threadIdx.x, lane = tid & 31, warp = tid >> 5;
    const int warpM = warp & 3, warpN = warp >> 2;
    const int gid = lane >> 2, tig = lane & 3;
    const int r0 = blockIdx.x * 128, col0 = blockIdx.y * 64;
    float acc[2][4][4];
#pragma unroll
    for (int mt = 0; mt < 2; mt++)
#pragma unroll
        for (int nt = 0; nt < 4; nt++)
#pragma unroll
            for (int r = 0; r < 4; r++) acc[mt][nt][r] = 0.f;

    for (int k0 = 0; k0 < K; k0 += 32) {
#pragma unroll
        for (int t = 0; t < 4; t++) {
            int li = tid + t * 256;
            int r = li >> 3, kq = li & 7;
            int row = r0 + r;
            float4 av = make_float4(0.f, 0.f, 0.f, 0.f);
            if (row < rows) av = *(const float4*)(A + (size_t)row * lda + k0 + kq * 4);
            *(float4*)&As[r][kq * 4] = av;
        }
#pragma unroll
        for (int t = 0; t < 2; t++) {
            int li = tid + t * 256;
            int kk = li >> 4, oq = li & 15;
            *(float4*)&Ws[kk][oq * 4] =
                *(const float4*)(W + (size_t)(k0 + kk) * wld + col0 + oq * 4);
        }
        __syncthreads();
#pragma unroll
        for (int ks = 0; ks < 4; ks++) {
            int kb = ks * 8;
            uint32_t ah[2][4], al[2][4];
#pragma unroll
            for (int mt = 0; mt < 2; mt++) {
                int ar = warpM * 32 + mt * 16 + gid;
                float f0 = As[ar][kb + tig];
                float f1 = As[ar + 8][kb + tig];
                float f2 = As[ar][kb + tig + 4];
                float f3 = As[ar + 8][kb + tig + 4];
                ah[mt][0] = f2tf(f0); al[mt][0] = f2tf(f0 - __uint_as_float(ah[mt][0]));
                ah[mt][1] = f2tf(f1); al[mt][1] = f2tf(f1 - __uint_as_float(ah[mt][1]));
                ah[mt][2] = f2tf(f2); al[mt][2] = f2tf(f2 - __uint_as_float(ah[mt][2]));
                ah[mt][3] = f2tf(f3); al[mt][3] = f2tf(f3 - __uint_as_float(ah[mt][3]));
            }
            uint32_t bh[4][2], bl[4][2];
#pragma unroll
            for (int nt = 0; nt < 4; nt++) {
                int bc = warpN * 32 + nt * 8 + gid;
                float g0 = Ws[kb + tig][bc];
                float g1 = Ws[kb + tig + 4][bc];
                bh[nt][0] = f2tf(g0); bl[nt][0] = f2tf(g0 - __uint_as_float(bh[nt][0]));
                bh[nt][1] = f2tf(g1); bl[nt][1] = f2tf(g1 - __uint_as_float(bh[nt][1]));
            }
#pragma unroll
            for (int mt = 0; mt < 2; mt++)
#pragma unroll
                for (int nt = 0; nt < 4; nt++) {
                    mma8(acc[mt][nt], ah[mt][0], ah[mt][1], ah[mt][2], ah[mt][3],
                         bl[nt][0], bl[nt][1]);
                    mma8(acc[mt][nt], al[mt][0], al[mt][1], al[mt][2], al[mt][3],
                         bh[nt][0], bh[nt][1]);
                    mma8(acc[mt][nt], ah[mt][0], ah[mt][1], ah[mt][2], ah[mt][3],
                         bh[nt][0], bh[nt][1]);
                }
        }
        __syncthreads();
    }
    // epilogue
#pragma unroll
    for (int mt = 0; mt < 2; mt++) {
        int rl = r0 + warpM * 32 + mt * 16 + gid;
#pragma unroll
        for (int half = 0; half < 2; half++) {
            int row = rl + half * 8;
            if (row >= rows) continue;
#pragma unroll
            for (int nt = 0; nt < 4; nt++) {
                int col = col0 + warpN * 32 + nt * 8 + tig * 2;
                float v0 = acc[mt][nt][half * 2 + 0];
                float v1 = acc[mt][nt][half * 2 + 1];
                if (bias) { v0 += bias[col]; v1 += bias[col + 1]; }
                if (ACT == 1) {
                    v0 = (v0 > 0.f) ? v0 : 0.01f * v0;
                    v1 = (v1 > 0.f) ? v1 : 0.01f * v1;
                }
                float2* cp = (float2*)(C + (size_t)row * ldc + col);
                if (ACCUM) { float2 o = *cp; v0 += o.x; v1 += o.y; }
                *cp = make_float2(v0, v1);
            }
        }
    }
}

// ---------------- outputs ----------------
__global__ void k_glob_sum(const int* __restrict__ batch) {
    int idx = blockIdx.x * blockDim.x + threadIdx.x;
    if (idx >= NN * D64) return;
    atomicAdd(&g_gsum[batch[idx >> 6] * D64 + (idx & 63)], g_h[idx]);
}

__global__ void k_glob_out(float* __restrict__ out) {
    int idx = blockIdx.x * blockDim.x + threadIdx.x;
    if (idx >= GG * D64) return;
    int g = idx >> 6;
    out[NN * D64 + idx] = g_gsum[idx] / fmaxf(g_cntn[g], 1.f) + g_h[NN * D64 + idx];
}

__global__ void k_ne_out(const int* __restrict__ ne0, const int* __restrict__ ne1,
                         float* __restrict__ out) {
    int idx = blockIdx.x * blockDim.x + threadIdx.x;
    if (idx >= NE_ * D64) return;
    int j = idx >> 6, d = idx & 63;
    out[(NN + GG) * D64 + idx] = g_h[ne0[j] * D64 + d] + g_h[ne1[j] * D64 + d];
}

__global__ void k_cleanup() {
    int idx = blockIdx.x * blockDim.x + threadIdx.x;
    if (idx < GG * D64) g_gsum[idx] = 0.f;
    if (idx < GG) g_cntn[idx] = 0.f;
}

// ---------------- host launcher ----------------
#define GETSYM(ptr, sym) do { void* _p; cudaGetSymbolAddress(&_p, sym); ptr = (decltype(ptr))_p; } while (0)

extern "C" void kernel_launch(void* const* d_in, const int* in_sizes, int n_in,
                              void* d_out, int out_size) {
    const float* x          = (const float*)d_in[0];
    const float* cond       = (const float*)d_in[1];
    const float* edge_attr  = (const float*)d_in[2];
    const int*   edge_index = (const int*)d_in[3];
    const int*   ne_index   = (const int*)d_in[4];
    const int*   batch      = (const int*)d_in[5];
    const float* gen_w  = (const float*)d_in[6];
    const float* gen_b  = (const float*)d_in[7];
    const float* q_w    = (const float*)d_in[8];
    const float* q_b    = (const float*)d_in[9];
    const float* k_w    = (const float*)d_in[10];
    const float* k_b    = (const float*)d_in[11];
    const float* v_w    = (const float*)d_in[12];
    const float* v_b    = (const float*)d_in[13];
    const float* e_w    = (const float*)d_in[14];
    const float* skip_w = (const float*)d_in[15];
    const float* skip_b = (const float*)d_in[16];
    const float* lin_w  = (const float*)d_in[17];
    const float* lin_b  = (const float*)d_in[18];
    const float* ff_w1  = (const float*)d_in[19];
    const float* ff_b1  = (const float*)d_in[20];
    const float* ff_w2  = (const float*)d_in[21];
    const float* ff_b2  = (const float*)d_in[22];
    float* out = (float*)d_out;

    float *h_p, *hn_p, *agg_p, *big_p, *qkvp_p, *lh_p, *ln2_p, *ffh_p;
    float *w2_p, *w3_p, *qpw_p, *swlw_p, *lw3_p, *wcat_p, *bcat_p, *wlin_p, *blb_p;
    GETSYM(h_p, g_h);       GETSYM(hn_p, g_hn);     GETSYM(agg_p, g_agg);
    GETSYM(big_p, g_big);   GETSYM(qkvp_p, g_qkvp); GETSYM(lh_p, g_lh);
    GETSYM(ln2_p, g_ln2);   GETSYM(ffh_p, g_ffh);
    GETSYM(w2_p, g_w2);     GETSYM(w3_p, g_w3);     GETSYM(qpw_p, g_qpw);
    GETSYM(swlw_p, g_swlw); GETSYM(lw3_p, g_lw3);   GETSYM(wcat_p, g_wcat);
    GETSYM(bcat_p, g_bcat); GETSYM(wlin_p, g_wlin); GETSYM(blb_p, g_blb);

    const int T = 256;
    const int GRID_N = CDIV(NAUG, 128);
    cudaStream_t st = 0;

    // ---- setup ----
    k_build_edges<<<CDIV(MM, T), T, 0, st>>>(edge_index, edge_index + EE, batch);
    k_scanA<<<NB_SCAN, 256, 0, st>>>();
    k_scanB<<<1, 256, 0, st>>>();
    k_scanC<<<NB_SCAN, 256, 0, st>>>();
    k_scatter<<<CDIV(MM, T), T, 0, st>>>();
    k_abatch<<<CDIV(NAUG, T), T, 0, st>>>(batch);
    k_cntn<<<CDIV(NN, T), T, 0, st>>>(batch);
    k_init_h<<<CDIV(NAUG * D64, T), T, 0, st>>>(x, cond);
    k_tail_ep<<<CDIV(2 * NN * D64, T), T, 0, st>>>();
    k_tail_csr<<<CDIV(NAUG * 32, T), T, 0, st>>>(edge_attr);

    // ---- layers ----
    for (int i = 0; i < LL; i++) {
        const float* gw  = gen_w  + (size_t)i * D64 * D64;
        const float* gb  = gen_b  + (size_t)i * D64;
        const float* qw  = q_w    + (size_t)i * HD * HD;
        const float* qb  = q_b    + (size_t)i * HD;
        const float* kw  = k_w    + (size_t)i * HD * HD;
        const float* kb  = k_b    + (size_t)i * HD;
        const float* vw  = v_w    + (size_t)i * HD * HD;
        const float* vb  = v_b    + (size_t)i * HD;
        const float* ew  = e_w    + (size_t)i * D64 * HD;
        const float* sw  = skip_w + (size_t)i * HD * HD;
        const float* sb  = skip_b + (size_t)i * HD;
        const float* lw  = lin_w  + (size_t)i * HD * D64;
        const float* lb  = lin_b  + (size_t)i * D64;
        const float* f1w = ff_w1  + (size_t)i * D64 * 4 * D64;
        const float* f1b = ff_b1  + (size_t)i * 4 * D64;
        const float* f2w = ff_w2  + (size_t)i * 4 * D64 * D64;
        const float* f2b = ff_b2  + (size_t)i * D64;

        // weight precomputes (fp32, tiny)
        k_build_w2<<<CDIV(HD * HD, T), T, 0, st>>>(ew);
        k_build_w3<<<CDIV(HD * HD, T), T, 0, st>>>(ew);
        k_gemm2<HD, HD, 0, 0><<<dim3(1, 1), T, 0, st>>>(qw, w2_p, nullptr, qpw_p, HD, HD, HD);
        k_gemm2<HD, D64, 0, 0><<<dim3(1, 1), T, 0, st>>>(sw, lw, nullptr, swlw_p, D64, HD, D64);
        k_gemm2<HD, D64, 0, 0><<<dim3(1, 1), T, 0, st>>>(w3_p, lw, nullptr, lw3_p, D64, HD, D64);
        k_biaslin<<<1, 64, 0, st>>>(sb, lw, lb);
        k_wcat<<<CDIV(HD * 512, T), T, 0, st>>>(qw, kw, vw);
        k_bcat<<<2, 256, 0, st>>>(qb, kb, vb);
        k_wlin<<<CDIV(384 * D64, T), T, 0, st>>>(lw);

        // LN1 -> hn + big[:, :64]
        k_ln_stats<<<CDIV(NAUG * 32, T), T, 0, st>>>(h_p);
        k_ln_final<<<1, GG, 0, st>>>();
        k_ln_apply2<<<CDIV(NAUG * D64, T), T, 0, st>>>(h_p);

        // gen_conv -> agg ; gemm -> big[:, 64:128]
        k_gen<<<CDIV(NN * 32, T), T, 0, st>>>(edge_attr);
        k_gen_v<<<GG, T, 0, st>>>(edge_attr);
        k_gemm_tc<0, 0><<<dim3(GRID_N, 1), T, 0, st>>>(agg_p, D64, gw, D64, gb,
                                                       big_p + 64, 384, NAUG, D64);

        // fused q|k|v|qp projection
        k_gemm_tc<0, 0><<<dim3(GRID_N, 8), T, 0, st>>>(big_p, 384, wcat_p, 512, bcat_p,
                                                       qkvp_p, 512, NAUG, HD);

        // attention -> big[:, 128:256] (t), big[:, 256:384] (we)
        k_attn1<<<CDIV(NN * 32, T), T, 0, st>>>(edge_attr);
        k_attn1_v<<<GG, T, 0, st>>>(edge_attr);
        k_attn2<<<CDIV(NN * 32, T), T, 0, st>>>(edge_attr);
        k_attn2_v<<<GG, T, 0, st>>>(edge_attr);

        // lh = big @ wlin + blb  (one GEMM for skip + lin + edge terms)
        k_gemm_tc<0, 0><<<dim3(GRID_N, 1), T, 0, st>>>(big_p, 384, wlin_p, D64, blb_p,
                                                       lh_p, D64, NAUG, 384);

        // LN2
        k_ln_stats<<<CDIV(NAUG * 32, T), T, 0, st>>>(lh_p);
        k_ln_final<<<1, GG, 0, st>>>();
        k_ln_apply<<<CDIV(NAUG * D64, T), T, 0, st>>>(lh_p, ln2_p);

        // FF + residual
        k_gemm_tc<1, 0><<<dim3(GRID_N, 4), T, 0, st>>>(ln2_p, D64, f1w, 256, f1b,
                                                       ffh_p, 256, NAUG, D64);
        k_gemm_tc<0, 1><<<dim3(GRID_N, 1), T, 0, st>>>(ffh_p, 256, f2w, D64, f2b,
                                                       h_p, D64, NAUG, 256);
    }

    // ---- outputs ----
    cudaMemcpyAsync(out, h_p, sizeof(float) * NN * D64, cudaMemcpyDeviceToDevice, st);
    k_glob_sum<<<CDIV(NN * D64, T), T, 0, st>>>(batch);
    k_glob_out<<<CDIV(GG * D64, T), T, 0, st>>>(out);
    k_ne_out<<<CDIV(NE_ * D64, T), T, 0, st>>>(ne_index, ne_index + NE_, out);
    k_cleanup<<<CDIV(GG * D64, T), T, 0, st>>>();
}

// round 5
// speedup vs baseline: 1.8703x; 1.0300x over previous
#include <cuda_runtime.h>
#include <math.h>
#include <stdint.h>

// Problem constants
#define D64   64
#define HH    2
#define HD    128
#define LL    3
#define NN    50000
#define GG    128
#define EE    600000
#define NE_   300000
#define NAUG  (NN + GG)          // 50128
#define M0    (EE + 2 * NN)      // 700000
#define MM    (M0 + NAUG)        // 750128
#define TAILR (MM - EE)          // 150128
#define NB_SCAN ((NAUG + 255) / 256)   // 196

#define CDIV(a, b) (((a) + (b) - 1) / (b))

// dynamic smem bytes for tf32 GEMM: (128*36 + 32*72) float2
#define GEMM_SMEM ((128 * 36 + 32 * 72) * 8)

// ---------------- device scratch (static, no allocs) ----------------
__device__ int    g_src[MM];
__device__ int    g_dst[MM];
__device__ int    g_deg[NAUG];
__device__ int    g_rowptr[NAUG + 1];
__device__ int    g_bsum[256];
__device__ int    g_fill[NAUG];
__device__ int    g_esrc[MM];
__device__ int    g_eid[MM];
__device__ float  g_tail[(size_t)TAILR * D64];   // e_aug rows >= EE
__device__ float  g_h[NAUG * D64];
__device__ float  g_hn[NAUG * D64];
__device__ float  g_agg[NAUG * D64];
__device__ float  g_big[(size_t)NAUG * 384];     // [cat(128) | t(128) | we(128)]
__device__ float  g_qkvp[(size_t)NAUG * 512];    // [q | k | v | qp]
__device__ float  g_lh[NAUG * D64];
__device__ float  g_ln2[NAUG * D64];
__device__ float  g_ffh[(size_t)NAUG * 256];
__device__ float  g_w2[HD * HD];
__device__ float  g_w3[HD * HD];
__device__ float  g_qpw[HD * HD];
__device__ float  g_swlw[HD * D64];
__device__ float  g_lw3[HD * D64];
__device__ float  g_wcat[HD * 512];
__device__ float  g_bcat[512];
__device__ float  g_wlin[384 * D64];
__device__ float  g_blb[D64];
__device__ float  g_cntn[GG];
__device__ double g_lsum[GG];
__device__ double g_lsumsq[GG];
__device__ float  g_mean[GG];
__device__ float  g_rstd[GG];
__device__ int    g_abatch[NAUG];
__device__ float  g_gsum[GG * D64];

// ---------------- setup kernels ----------------
__global__ void k_build_edges(const int* __restrict__ ei0, const int* __restrict__ ei1,
                              const int* __restrict__ batch) {
    int m = blockIdx.x * blockDim.x + threadIdx.x;
    if (m >= MM) return;
    int s, d;
    if (m < EE)               { s = ei0[m]; d = ei1[m]; }
    else if (m < EE + NN)     { int i = m - EE;          s = i;             d = batch[i] + NN; }
    else if (m < EE + 2 * NN) { int i = m - EE - NN;     s = batch[i] + NN; d = i; }
    else                      { int i = m - EE - 2 * NN; s = i;             d = i; }
    g_src[m] = s; g_dst[m] = d;
    atomicAdd(&g_deg[d], 1);
}

__global__ void k_scanA() {
    __shared__ int sh[256];
    int t = threadIdx.x;
    int i = blockIdx.x * 256 + t;
    int v = (i < NAUG) ? g_deg[i] : 0;
    sh[t] = v;
    __syncthreads();
    for (int off = 1; off < 256; off <<= 1) {
        int a = (t >= off) ? sh[t - off] : 0;
        __syncthreads();
        sh[t] += a;
        __syncthreads();
    }
    if (i < NAUG) g_rowptr[i] = sh[t] - v;
    if (t == 255) g_bsum[blockIdx.x] = sh[255];
}

__global__ void k_scanB() {
    __shared__ int sh[256];
    int t = threadIdx.x;
    int v = (t < NB_SCAN) ? g_bsum[t] : 0;
    sh[t] = v;
    __syncthreads();
    for (int off = 1; off < 256; off <<= 1) {
        int a = (t >= off) ? sh[t - off] : 0;
        __syncthreads();
        sh[t] += a;
        __syncthreads();
    }
    if (t < NB_SCAN) g_bsum[t] = sh[t] - v;
}

__global__ void k_scanC() {
    int i = blockIdx.x * 256 + threadIdx.x;
    if (i < NAUG) {
        int r = g_rowptr[i] + g_bsum[i >> 8];
        g_rowptr[i] = r;
        g_fill[i] = r;
        g_deg[i] = 0;                 // self-clean
    }
    if (i == 0) g_rowptr[NAUG] = MM;
}

__global__ void k_scatter() {
    int m = blockIdx.x * blockDim.x + threadIdx.x;
    if (m >= MM) return;
    int pos = atomicAdd(&g_fill[g_dst[m]], 1);
    g_esrc[pos] = g_src[m];
    g_eid[pos]  = m;
}

__global__ void k_abatch(const int* __restrict__ batch) {
    int i = blockIdx.x * blockDim.x + threadIdx.x;
    if (i >= NAUG) return;
    g_abatch[i] = (i < NN) ? batch[i] : (i - NN);
}

__global__ void k_cntn(const int* __restrict__ batch) {
    int i = blockIdx.x * blockDim.x + threadIdx.x;
    if (i >= NN) return;
    atomicAdd(&g_cntn[batch[i]], 1.f);
}

__global__ void k_init_h(const float* __restrict__ x, const float* __restrict__ cond) {
    int idx = blockIdx.x * blockDim.x + threadIdx.x;
    if (idx >= NAUG * D64) return;
    g_h[idx] = (idx < NN * D64) ? x[idx] : cond[idx - NN * D64];
}

__global__ void k_tail_ep() {
    int idx = blockIdx.x * blockDim.x + threadIdx.x;
    if (idx >= 2 * NN * D64) return;
    g_tail[idx] = ((idx & 63) == 0) ? 1.f : 0.f;
}

__global__ void k_tail_csr(const float* __restrict__ edge_attr) {
    int i = (blockIdx.x * blockDim.x + threadIdx.x) >> 5;
    int lane = threadIdx.x & 31;
    if (i >= NAUG) return;
    float2 acc = {0.f, 0.f};
    float cnt = 0.f;
    int e0 = g_rowptr[i], e1 = g_rowptr[i + 1];
    for (int e = e0; e < e1; e++) {
        int m = g_eid[e];
        if (m < EE) {
            float2 ev = ((const float2*)(edge_attr + (size_t)m * D64))[lane];
            acc.x += ev.x; acc.y += ev.y;
            cnt += 1.f;
        } else if (m < M0) {
            if (lane == 0) acc.x += 1.f;
            cnt += 1.f;
        }
    }
    float invc = 1.f / fmaxf(cnt, 1.f);
    float2 o = {acc.x * invc, acc.y * invc};
    ((float2*)(g_tail + (size_t)(2 * NN + i) * D64))[lane] = o;
}

// ---------------- graph layernorm ----------------
__global__ void k_ln_stats(const float* __restrict__ X) {
    int i = (blockIdx.x * blockDim.x + threadIdx.x) >> 5;
    int lane = threadIdx.x & 31;
    if (i >= NAUG) return;
    float2 v = ((const float2*)(X + (size_t)i * D64))[lane];
    float s  = v.x + v.y;
    float ss = v.x * v.x + v.y * v.y;
#pragma unroll
    for (int off = 16; off; off >>= 1) {
        s  += __shfl_xor_sync(0xffffffffu, s, off);
        ss += __shfl_xor_sync(0xffffffffu, ss, off);
    }
    if (lane == 0) {
        int b = g_abatch[i];
        atomicAdd(&g_lsum[b], (double)s);
        atomicAdd(&g_lsumsq[b], (double)ss);
    }
}

__global__ void k_ln_final() {
    int g = threadIdx.x;
    if (g >= GG) return;
    double norm = (double)fmaxf(g_cntn[g] + 1.f, 1.f) * D64;
    double mean = g_lsum[g] / norm;
    double var  = g_lsumsq[g] / norm - mean * mean;
    g_mean[g] = (float)mean;
    g_rstd[g] = rsqrtf((float)var + 1e-5f);
    g_lsum[g] = 0.0;            // self-clean
    g_lsumsq[g] = 0.0;
}

// writes hn AND big[:, 0:64] (cat left half)
__global__ void k_ln_apply2(const float* __restrict__ X) {
    int idx = blockIdx.x * blockDim.x + threadIdx.x;
    if (idx >= NAUG * D64) return;
    int i = idx >> 6, d = idx & 63;
    int b = g_abatch[i];
    float v = (X[idx] - g_mean[b]) * g_rstd[b];
    g_hn[idx] = v;
    g_big[(size_t)i * 384 + d] = v;
}

__global__ void k_ln_apply(const float* __restrict__ X, float* __restrict__ Y) {
    int idx = blockIdx.x * blockDim.x + threadIdx.x;
    if (idx >= NAUG * D64) return;
    int b = g_abatch[idx >> 6];
    Y[idx] = (X[idx] - g_mean[b]) * g_rstd[b];
}

// ---------------- gen_conv: regular nodes (warp each) ----------------
__global__ void k_gen(const float* __restrict__ edge_attr) {
    int i = (blockIdx.x * blockDim.x + threadIdx.x) >> 5;
    int lane = threadIdx.x & 31;
    if (i >= NN) return;
    float2 acc = {0.f, 0.f};
    int e0 = g_rowptr[i], e1 = g_rowptr[i + 1];
    for (int e = e0; e < e1; e++) {
        int s = g_esrc[e], m = g_eid[e];
        const float* ep = (m < EE) ? edge_attr + (size_t)m * D64
                                   : g_tail + (size_t)(m - EE) * D64;
        float2 ev = ((const float2*)ep)[lane];
        float2 hv = ((const float2*)(g_hn + (size_t)s * D64))[lane];
        acc.x += fmaxf(hv.x + ev.x, 0.f) + 1e-7f;
        acc.y += fmaxf(hv.y + ev.y, 0.f) + 1e-7f;
    }
    float2 hi = ((const float2*)(g_hn + (size_t)i * D64))[lane];
    float2 o = {acc.x + hi.x, acc.y + hi.y};
    ((float2*)(g_agg + (size_t)i * D64))[lane] = o;
}

__global__ void k_gen_v(const float* __restrict__ edge_attr) {
    __shared__ float sa[64];
    int i = NN + blockIdx.x;
    int tid = threadIdx.x, lane = tid & 31, wid = tid >> 5;
    if (tid < 64) sa[tid] = 0.f;
    __syncthreads();
    int e0 = g_rowptr[i], e1 = g_rowptr[i + 1];
    float2 acc = {0.f, 0.f};
    for (int e = e0 + wid; e < e1; e += 8) {
        int s = g_esrc[e], m = g_eid[e];
        const float* ep = (m < EE) ? edge_attr + (size_t)m * D64
                                   : g_tail + (size_t)(m - EE) * D64;
        float2 ev = ((const float2*)ep)[lane];
        float2 hv = ((const float2*)(g_hn + (size_t)s * D64))[lane];
        acc.x += fmaxf(hv.x + ev.x, 0.f) + 1e-7f;
        acc.y += fmaxf(hv.y + ev.y, 0.f) + 1e-7f;
    }
    atomicAdd(&sa[2 * lane],     acc.x);
    atomicAdd(&sa[2 * lane + 1], acc.y);
    __syncthreads();
    if (tid < 64) g_agg[(size_t)i * D64 + tid] = sa[tid] + g_hn[(size_t)i * D64 + tid];
}

// ---------------- fused single-pass attention (online softmax) ----------------
__global__ void k_attn(const float* __restrict__ edge_attr) {
    int i = (blockIdx.x * blockDim.x + threadIdx.x) >> 5;
    int lane = threadIdx.x & 31;
    if (i >= NN) return;
    int el = lane & 15;
    float4 q4  = *(const float4*)(g_qkvp + (size_t)i * 512 + 4 * lane);
    float4 qp4 = *(const float4*)(g_qkvp + (size_t)i * 512 + 384 + 4 * lane);
    int e0 = g_rowptr[i], e1 = g_rowptr[i + 1];
    float mx = -INFINITY, sum = 0.f;
    float4 vacc = {0.f, 0.f, 0.f, 0.f};
    float4 eacc = {0.f, 0.f, 0.f, 0.f};
    for (int e = e0; e < e1; e++) {
        int s = g_esrc[e], m = g_eid[e];
        const float* ep = (m < EE) ? edge_attr + (size_t)m * D64
                                   : g_tail + (size_t)(m - EE) * D64;
        float4 k4 = *(const float4*)(g_qkvp + (size_t)s * 512 + 128 + 4 * lane);
        float4 e4 = *(const float4*)(ep + 4 * el);
        float p = q4.x * k4.x + q4.y * k4.y + q4.z * k4.z + q4.w * k4.w
                + qp4.x * e4.x + qp4.y * e4.y + qp4.z * e4.z + qp4.w * e4.w;
        p += __shfl_xor_sync(0xffffffffu, p, 1);
        p += __shfl_xor_sync(0xffffffffu, p, 2);
        p += __shfl_xor_sync(0xffffffffu, p, 4);
        p += __shfl_xor_sync(0xffffffffu, p, 8);
        float a = p * 0.125f;
        if (a > mx) {
            float sc = expf(mx - a);  // first iter: expf(-inf)=0 zeroes nothing (accs are 0)
            sum *= sc;
            vacc.x *= sc; vacc.y *= sc; vacc.z *= sc; vacc.w *= sc;
            eacc.x *= sc; eacc.y *= sc; eacc.z *= sc; eacc.w *= sc;
            mx = a;
        }
        float w = expf(a - mx);
        sum += w;
        float4 v4 = *(const float4*)(g_qkvp + (size_t)s * 512 + 256 + 4 * lane);
        vacc.x += w * v4.x; vacc.y += w * v4.y; vacc.z += w * v4.z; vacc.w += w * v4.w;
        eacc.x += w * e4.x; eacc.y += w * e4.y; eacc.z += w * e4.z; eacc.w += w * e4.w;
    }
    float inv = 1.f / (sum + 1e-16f);
    float4 to = {vacc.x * inv, vacc.y * inv, vacc.z * inv, vacc.w * inv};
    float4 wo = {eacc.x * inv, eacc.y * inv, eacc.z * inv, eacc.w * inv};
    *(float4*)(g_big + (size_t)i * 384 + 128 + 4 * lane) = to;
    *(float4*)(g_big + (size_t)i * 384 + 256 + 4 * lane) = wo;
}

__global__ void k_attn_v(const float* __restrict__ edge_attr) {
    __shared__ float sv[128];
    __shared__ float se[128];
    __shared__ float ssg[2];
    __shared__ float swmx[16];
    __shared__ float gmx[2];
    int i = NN + blockIdx.x;
    int tid = threadIdx.x, lane = tid & 31, wid = tid >> 5;
    int el = lane & 15;
    int hh = lane >> 4;
    if (tid < 128) { sv[tid] = 0.f; se[tid] = 0.f; }
    if (tid < 2) ssg[tid] = 0.f;
    __syncthreads();
    float4 q4  = *(const float4*)(g_qkvp + (size_t)i * 512 + 4 * lane);
    float4 qp4 = *(const float4*)(g_qkvp + (size_t)i * 512 + 384 + 4 * lane);
    int e0 = g_rowptr[i], e1 = g_rowptr[i + 1];
    float mx = -INFINITY, sum = 0.f;
    float4 vacc = {0.f, 0.f, 0.f, 0.f};
    float4 eacc = {0.f, 0.f, 0.f, 0.f};
    for (int e = e0 + wid; e < e1; e += 8) {
        int s = g_esrc[e], m = g_eid[e];
        const float* ep = (m < EE) ? edge_attr + (size_t)m * D64
                                   : g_tail + (size_t)(m - EE) * D64;
        float4 k4 = *(const float4*)(g_qkvp + (size_t)s * 512 + 128 + 4 * lane);
        float4 e4 = *(const float4*)(ep + 4 * el);
        float p = q4.x * k4.x + q4.y * k4.y + q4.z * k4.z + q4.w * k4.w
                + qp4.x * e4.x + qp4.y * e4.y + qp4.z * e4.z + qp4.w * e4.w;
        p += __shfl_xor_sync(0xffffffffu, p, 1);
        p += __shfl_xor_sync(0xffffffffu, p, 2);
        p += __shfl_xor_sync(0xffffffffu, p, 4);
        p += __shfl_xor_sync(0xffffffffu, p, 8);
        float a = p * 0.125f;
        if (a > mx) {
            float sc = expf(mx - a);
            sum *= sc;
            vacc.x *= sc; vacc.y *= sc; vacc.z *= sc; vacc.w *= sc;
            eacc.x *= sc; eacc.y *= sc; eacc.z *= sc; eacc.w *= sc;
            mx = a;
        }
        float w = expf(a - mx);
        sum += w;
        float4 v4 = *(const float4*)(g_qkvp + (size_t)s * 512 + 256 + 4 * lane);
        vacc.x += w * v4.x; vacc.y += w * v4.y; vacc.z += w * v4.z; vacc.w += w * v4.w;
        eacc.x += w * e4.x; eacc.y += w * e4.y; eacc.z += w * e4.z; eacc.w += w * e4.w;
    }
    if (el == 0) swmx[wid * 2 + hh] = mx;
    __syncthreads();
    if (tid < 2) {
        float m = -INFINITY;
#pragma unroll
        for (int w = 0; w < 8; w++) m = fmaxf(m, swmx[w * 2 + tid]);
        gmx[tid] = m;
    }
    __syncthreads();
    float sc = expf(mx - gmx[hh]);  // mx=-inf (warp had no edges) -> sc=0, zero contribution
    atomicAdd(&sv[4 * lane],     vacc.x * sc); atomicAdd(&sv[4 * lane + 1], vacc.y * sc);
    atomicAdd(&sv[4 * lane + 2], vacc.z * sc); atomicAdd(&sv[4 * lane + 3], vacc.w * sc);
    atomicAdd(&se[4 * lane],     eacc.x * sc); atomicAdd(&se[4 * lane + 1], eacc.y * sc);
    atomicAdd(&se[4 * lane + 2], eacc.z * sc); atomicAdd(&se[4 * lane + 3], eacc.w * sc);
    if (el == 0) atomicAdd(&ssg[hh], sum * sc);
    __syncthreads();
    if (tid < 128) {
        float inv = 1.f / (ssg[tid >> 6] + 1e-16f);
        g_big[(size_t)i * 384 + 128 + tid] = sv[tid] * inv;
        g_big[(size_t)i * 384 + 256 + tid] = se[tid] * inv;
    }
}

// ---------------- block-diagonal weight builders ----------------
__global__ void k_build_w2(const float* __restrict__ ew) {
    int idx = blockIdx.x * blockDim.x + threadIdx.x;
    if (idx >= HD * HD) return;
    int r = idx >> 7, o = idx & 127;
    int h = r >> 6, d = r & 63, h2 = o >> 6, c = o & 63;
    g_w2[idx] = (h == h2) ? ew[(size_t)c * HD + h * 64 + d] : 0.f;
}
__global__ void k_build_w3(const float* __restrict__ ew) {
    int idx = blockIdx.x * blockDim.x + threadIdx.x;
    if (idx >= HD * HD) return;
    int r = idx >> 7, o = idx & 127;
    int h = r >> 6, c = r & 63, h2 = o >> 6, o2 = o & 63;
    g_w3[idx] = (h == h2) ? ew[(size_t)c * HD + h2 * 64 + o2] : 0.f;
}

__global__ void k_biaslin(const float* __restrict__ sb, const float* __restrict__ lw,
                          const float* __restrict__ lb) {
    int o = threadIdx.x;
    if (o >= D64) return;
    float acc = lb[o];
    for (int k2 = 0; k2 < HD; k2++) acc += sb[k2] * lw[(size_t)k2 * D64 + o];
    g_blb[o] = acc;
}

// wcat = [qw | kw | vw | qw@W2]  (128 x 512)
__global__ void k_wcat(const float* __restrict__ qw, const float* __restrict__ kw,
                       const float* __restrict__ vw) {
    int idx = blockIdx.x * blockDim.x + threadIdx.x;
    if (idx >= HD * 512) return;
    int r = idx >> 9, c = idx & 511;
    float v;
    if (c < 128)      v = qw[r * HD + c];
    else if (c < 256) v = kw[r * HD + c - 128];
    else if (c < 384) v = vw[r * HD + c - 256];
    else              v = g_qpw[r * HD + c - 384];
    g_wcat[idx] = v;
}

// bcat = [qb | kb | vb | qb@W2]
__global__ void k_bcat(const float* __restrict__ qb, const float* __restrict__ kb,
                       const float* __restrict__ vb) {
    int c = blockIdx.x * blockDim.x + threadIdx.x;
    if (c >= 512) return;
    float v;
    if (c < 128)      v = qb[c];
    else if (c < 256) v = kb[c - 128];
    else if (c < 384) v = vb[c - 256];
    else {
        int o = c - 384;
        float a = 0.f;
        for (int d = 0; d < HD; d++) a += qb[d] * g_w2[d * HD + o];
        v = a;
    }
    g_bcat[c] = v;
}

// wlin = [sw@lw ; lw ; W3@lw]  (384 x 64), matching big = [cat|t|we]
__global__ void k_wlin(const float* __restrict__ lw) {
    int idx = blockIdx.x * blockDim.x + threadIdx.x;
    if (idx >= 384 * D64) return;
    int r = idx >> 6, c = idx & 63;
    float v;
    if (r < 128)      v = g_swlw[r * D64 + c];
    else if (r < 256) v = lw[(size_t)(r - 128) * D64 + c];
    else              v = g_lw3[(r - 256) * D64 + c];
    g_wlin[idx] = v;
}

// ---------------- fp32 GEMM (weight prep only; rows ~128) ----------------
template <int IN, int OUTT, int ACT, int ACCUM>
__global__ __launch_bounds__(256) void k_gemm2(
        const float* __restrict__ A, const float* __restrict__ W,
        const float* __restrict__ bias, float* __restrict__ C,
        int ldc, int rows, int wld) {
    __shared__ float As[32][132];
    __shared__ float Ws[32][OUTT];
    constexpr int CT = OUTT / 16;
    const int tid = threadIdx.x;
    const int tx = tid & 15;
    const int ty = tid >> 4;
    const int r0 = blockIdx.x * 128;
    const int col0 = blockIdx.y * OUTT;
    float acc[8][CT];
#pragma unroll
    for (int i = 0; i < 8; i++)
#pragma unroll
        for (int j = 0; j < CT; j++) acc[i][j] = 0.f;

    for (int k0 = 0; k0 < IN; k0 += 32) {
#pragma unroll
        for (int t = 0; t < 4; t++) {
            int li = tid + t * 256;
            int r = li >> 3, kq = li & 7;
            int row = r0 + r;
            float4 av = make_float4(0.f, 0.f, 0.f, 0.f);
            if (row < rows) av = *(const float4*)(A + (size_t)row * IN + k0 + kq * 4);
            As[kq * 4 + 0][r] = av.x;
            As[kq * 4 + 1][r] = av.y;
            As[kq * 4 + 2][r] = av.z;
            As[kq * 4 + 3][r] = av.w;
        }
#pragma unroll
        for (int t = 0; t < OUTT / 32; t++) {
            int li = tid + t * 256;
            int kk = li / (OUTT / 4), oq = li % (OUTT / 4);
            ((float4*)(&Ws[kk][0]))[oq] =
                *(const float4*)(W + (size_t)(k0 + kk) * wld + col0 + oq * 4);
        }
        __syncthreads();
#pragma unroll
        for (int kk = 0; kk < 32; kk++) {
            float4 a0 = *(const float4*)&As[kk][ty * 8];
            float4 a1 = *(const float4*)&As[kk][ty * 8 + 4];
            float av[8] = {a0.x, a0.y, a0.z, a0.w, a1.x, a1.y, a1.z, a1.w};
            float wv[CT];
            float4 w0 = *(const float4*)&Ws[kk][tx * CT];
            wv[0] = w0.x; wv[1] = w0.y; wv[2] = w0.z; wv[3] = w0.w;
            if (CT == 8) {
                float4 w1 = *(const float4*)&Ws[kk][tx * CT + 4];
                wv[4] = w1.x; wv[5] = w1.y; wv[6] = w1.z; wv[7] = w1.w;
            }
#pragma unroll
            for (int i = 0; i < 8; i++)
#pragma unroll
                for (int j = 0; j < CT; j++) acc[i][j] += av[i] * wv[j];
        }
        __syncthreads();
    }
#pragma unroll
    for (int i = 0; i < 8; i++) {
        int row = r0 + ty * 8 + i;
        if (row >= rows) continue;
#pragma unroll
        for (int j = 0; j < CT; j++) {
            int col = col0 + tx * CT + j;
            float v = acc[i][j] + (bias ? bias[col] : 0.f);
            if (ACT == 1) v = (v > 0.f) ? v : 0.01f * v;
            float* cp = &C[(size_t)row * ldc + col];
            if (ACCUM) *cp += v; else *cp = v;
        }
    }
}

// ---------------- 3xTF32 tensor-core GEMM (hi/lo split in smem) ----------------
__device__ __forceinline__ uint32_t f2tf(float f) {
    uint32_t u;
    asm("cvt.rna.tf32.f32 %0, %1;" : "=r"(u) : "f"(f));
    return u;
}

__device__ __forceinline__ float2 split_tf(float f) {
    uint32_t h = f2tf(f);
    float hf = __uint_as_float(h);
    uint32_t l = f2tf(f - hf);
    return make_float2(hf, __uint_as_float(l));
}

__device__ __forceinline__ void mma8(float* c, uint32_t a0, uint32_t a1, uint32_t a2,
                                     uint32_t a3, uint32_t b0, uint32_t b1) {
    asm volatile(
        "mma.sync.aligned.m16n8k8.row.col.f32.tf32.tf32.f32 "
        "{%0,%1,%2,%3}, {%4,%5,%6,%7}, {%8,%9}, {%0,%1,%2,%3};"
        : "+f"(c[0]), "+f"(c[1]), "+f"(c[2]), "+f"(c[3])
        : "r"(a0), "r"(a1), "r"(a2), "r"(a3), "r"(b0), "r"(b1));
}

// C[rows x OUT] = act(A[rows x K](lda) @ W[K x OUT](wld) + bias)
// block: 256 thr = 8 warps (4 m x 2 n), tile 128 x 64, K step 32.
// dynamic smem: As2 128x36 float2 (hi,lo) + Ws2 32x72 float2.
template <int ACT, int ACCUM>
__global__ __launch_bounds__(256) void k_gemm_tc(
        const float* __restrict__ A, int lda,
        const float* __restrict__ W, int wld,
        const float* __restrict__ bias, float* __restrict__ C,
        int ldc, int rows, int K) {
    extern __shared__ __align__(16) float2 sm2[];
    float2 (*As2)[36] = reinterpret_cast<float2(*)[36]>(sm2);
    float2 (*Ws2)[72] = reinterpret_cast<float2(*)[72]>(sm2 + 128 * 36);
    const int tid = threadIdx.x, lane = tid & 31, warp = tid >> 5;
    const int warpM = warp & 3, warpN = warp >> 2;
    const int gid = lane >> 2, tig = lane & 3;
    const int r0 = blockIdx.x * 128, col0 = blockIdx.y * 64;
    float acc[2][4][4];
#pragma unroll
    for (int mt = 0; mt < 2; mt++)
#pragma unroll
        for (int nt = 0; nt < 4; nt++)
#pragma unroll
            for (int r = 0; r < 4; r++) acc[mt][nt][r] = 0.f;

    for (int k0 = 0; k0 < K; k0 += 32) {
        // A tile: load fp32, split to (hi,lo) tf32 pair once per element
#pragma unroll
        for (int t = 0; t < 4; t++) {
            int li = tid + t * 256;
            int r = li >> 3, kq = li & 7;
            int row = r0 + r;
            float4 av = make_float4(0.f, 0.f, 0.f, 0.f);
            if (row < rows) av = *(const float4*)(A + (size_t)row * lda + k0 + kq * 4);
            As2[r][kq * 4 + 0] = split_tf(av.x);
            As2[r][kq * 4 + 1] = split_tf(av.y);
            As2[r][kq * 4 + 2] = split_tf(av.z);
            As2[r][kq * 4 + 3] = split_tf(av.w);
        }
        // W tile: same
#pragma unroll
        for (int t = 0; t < 2; t++) {
            int li = tid + t * 256;
            int kk = li >> 4, oq = li & 15;
            float4 wv = *(const float4*)(W + (size_t)(k0 + kk) * wld + col0 + oq * 4);
            Ws2[kk][oq * 4 + 0] = split_tf(wv.x);
            Ws2[kk][oq * 4 + 1] = split_tf(wv.y);
            Ws2[kk][oq * 4 + 2] = split_tf(wv.z);
            Ws2[kk][oq * 4 + 3] = split_tf(wv.w);
        }
        __syncthreads();
#pragma unroll
        for (int ks = 0; ks < 4; ks++) {
            int kb = ks * 8;
            uint32_t ah[2][4], al[2][4];
#pragma unroll
            for (int mt = 0; mt < 2; mt++) {
                int ar = warpM * 32 + mt * 16 + gid;
                float2 f0 = As2[ar][kb + tig];
                float2 f1 = As2[ar + 8][kb + tig];
                float2 f2 = As2[ar][kb + tig + 4];
                float2 f3 = As2[ar + 8][kb + tig + 4];
                ah[mt][0] = __float_as_uint(f0.x); al[mt][0] = __float_as_uint(f0.y);
                ah[mt][1] = __float_as_uint(f1.x); al[mt][1] = __float_as_uint(f1.y);
                ah[mt][2] = __float_as_uint(f2.x); al[mt][2] = __float_as_uint(f2.y);
                ah[mt][3] = __float_as_uint(f3.x); al[mt][3] = __float_as_uint(f3.y);
            }
            uint32_t bh[4][2], bl[4][2];
#pragma unroll
            for (int nt = 0; nt < 4; nt++) {
                int bc = warpN * 32 + nt * 8 + gid;
                float2 g0 = Ws2[kb + tig][bc];
                float2 g1 = Ws2[kb + tig + 4][bc];
                bh[nt][0] = __float_as_uint(g0.x); bl[nt][0] = __float_as_uint(g0.y);
                bh[nt][1] = __float_as_uint(g1.x); bl[nt][1] = __float_as_uint(g1.y);
            }
#pragma unroll
            for (int mt = 0; mt < 2; mt++)
#pragma unroll
                for (int nt = 0; nt < 4; nt++) {
                    mma8(acc[mt][nt], ah[mt][0], ah[mt][1], ah[mt][2], ah[mt][3],
                         bl[nt][0], bl[nt][1]);
                    mma8(acc[mt][nt], al[mt][0], al[mt][1], al[mt][2], al[mt][3],
                         bh[nt][0], bh[nt][1]);
                    mma8(acc[mt][nt], ah[mt][0], ah[mt][1], ah[mt][2], ah[mt][3],
                         bh[nt][0], bh[nt][1]);
                }
        }
        __syncthreads();
    }
    // epilogue
#pragma unroll
    for (int mt = 0; mt < 2; mt++) {
        int rl = r0 + warpM * 32 + mt * 16 + gid;
#pragma unroll
        for (int half = 0; half < 2; half++) {
            int row = rl + half * 8;
            if (row >= rows) continue;
#pragma unroll
            for (int nt = 0; nt < 4; nt++) {
                int col = col0 + warpN * 32 + nt * 8 + tig * 2;
                float v0 = acc[mt][nt][half * 2 + 0];
                float v1 = acc[mt][nt][half * 2 + 1];
                if (bias) { v0 += bias[col]; v1 += bias[col + 1]; }
                if (ACT == 1) {
                    v0 = (v0 > 0.f) ? v0 : 0.01f * v0;
                    v1 = (v1 > 0.f) ? v1 : 0.01f * v1;
                }
                float2* cp = (float2*)(C + (size_t)row * ldc + col);
                if (ACCUM) { float2 o = *cp; v0 += o.x; v1 += o.y; }
                *cp = make_float2(v0, v1);
            }
        }
    }
}

// ---------------- outputs ----------------
__global__ void k_glob_sum(const int* __restrict__ batch) {
    int idx = blockIdx.x * blockDim.x + threadIdx.x;
    if (idx >= NN * D64) return;
    atomicAdd(&g_gsum[batch[idx >> 6] * D64 + (idx & 63)], g_h[idx]);
}

__global__ void k_glob_out(float* __restrict__ out) {
    int idx = blockIdx.x * blockDim.x + threadIdx.x;
    if (idx >= GG * D64) return;
    int g = idx >> 6;
    out[NN * D64 + idx] = g_gsum[idx] / fmaxf(g_cntn[g], 1.f) + g_h[NN * D64 + idx];
}

__global__ void k_ne_out(const int* __restrict__ ne0, const int* __restrict__ ne1,
                         float* __restrict__ out) {
    int idx = blockIdx.x * blockDim.x + threadIdx.x;
    if (idx >= NE_ * D64) return;
    int j = idx >> 6, d = idx & 63;
    out[(NN + GG) * D64 + idx] = g_h[ne0[j] * D64 + d] + g_h[ne1[j] * D64 + d];
}

__global__ void k_cleanup() {
    int idx = blockIdx.x * blockDim.x + threadIdx.x;
    if (idx < GG * D64) g_gsum[idx] = 0.f;
    if (idx < GG) g_cntn[idx] = 0.f;
}

// ---------------- host launcher ----------------
#define GETSYM(ptr, sym) do { void* _p; cudaGetSymbolAddress(&_p, sym); ptr = (decltype(ptr))_p; } while (0)

extern "C" void kernel_launch(void* const* d_in, const int* in_sizes, int n_in,
                              void* d_out, int out_size) {
    const float* x          = (const float*)d_in[0];
    const float* cond       = (const float*)d_in[1];
    const float* edge_attr  = (const float*)d_in[2];
    const int*   edge_index = (const int*)d_in[3];
    const int*   ne_index   = (const int*)d_in[4];
    const int*   batch      = (const int*)d_in[5];
    const float* gen_w  = (const float*)d_in[6];
    const float* gen_b  = (const float*)d_in[7];
    const float* q_w    = (const float*)d_in[8];
    const float* q_b    = (const float*)d_in[9];
    const float* k_w    = (const float*)d_in[10];
    const float* k_b    = (const float*)d_in[11];
    const float* v_w    = (const float*)d_in[12];
    const float* v_b    = (const float*)d_in[13];
    const float* e_w    = (const float*)d_in[14];
    const float* skip_w = (const float*)d_in[15];
    const float* skip_b = (const float*)d_in[16];
    const float* lin_w  = (const float*)d_in[17];
    const float* lin_b  = (const float*)d_in[18];
    const float* ff_w1  = (const float*)d_in[19];
    const float* ff_b1  = (const float*)d_in[20];
    const float* ff_w2  = (const float*)d_in[21];
    const float* ff_b2  = (const float*)d_in[22];
    float* out = (float*)d_out;

    float *h_p, *hn_p, *agg_p, *big_p, *qkvp_p, *lh_p, *ln2_p, *ffh_p;
    float *w2_p, *w3_p, *qpw_p, *swlw_p, *lw3_p, *wcat_p, *bcat_p, *wlin_p, *blb_p;
    GETSYM(h_p, g_h);       GETSYM(hn_p, g_hn);     GETSYM(agg_p, g_agg);
    GETSYM(big_p, g_big);   GETSYM(qkvp_p, g_qkvp); GETSYM(lh_p, g_lh);
    GETSYM(ln2_p, g_ln2);   GETSYM(ffh_p, g_ffh);
    GETSYM(w2_p, g_w2);     GETSYM(w3_p, g_w3);     GETSYM(qpw_p, g_qpw);
    GETSYM(swlw_p, g_swlw); GETSYM(lw3_p, g_lw3);   GETSYM(wcat_p, g_wcat);
    GETSYM(bcat_p, g_bcat); GETSYM(wlin_p, g_wlin); GETSYM(blb_p, g_blb);

    // raise dynamic smem limit for the tf32 GEMM instantiations (idempotent)
    cudaFuncSetAttribute(k_gemm_tc<0, 0>, cudaFuncAttributeMaxDynamicSharedMemorySize, GEMM_SMEM);
    cudaFuncSetAttribute(k_gemm_tc<1, 0>, cudaFuncAttributeMaxDynamicSharedMemorySize, GEMM_SMEM);
    cudaFuncSetAttribute(k_gemm_tc<0, 1>, cudaFuncAttributeMaxDynamicSharedMemorySize, GEMM_SMEM);

    const int T = 256;
    const int GRID_N = CDIV(NAUG, 128);
    cudaStream_t st = 0;

    // ---- setup ----
    k_build_edges<<<CDIV(MM, T), T, 0, st>>>(edge_index, edge_index + EE, batch);
    k_scanA<<<NB_SCAN, 256, 0, st>>>();
    k_scanB<<<1, 256, 0, st>>>();
    k_scanC<<<NB_SCAN, 256, 0, st>>>();
    k_scatter<<<CDIV(MM, T), T, 0, st>>>();
    k_abatch<<<CDIV(NAUG, T), T, 0, st>>>(batch);
    k_cntn<<<CDIV(NN, T), T, 0, st>>>(batch);
    k_init_h<<<CDIV(NAUG * D64, T), T, 0, st>>>(x, cond);
    k_tail_ep<<<CDIV(2 * NN * D64, T), T, 0, st>>>();
    k_tail_csr<<<CDIV(NAUG * 32, T), T, 0, st>>>(edge_attr);

    // ---- layers ----
    for (int i = 0; i < LL; i++) {
        const float* gw  = gen_w  + (size_t)i * D64 * D64;
        const float* gb  = gen_b  + (size_t)i * D64;
        const float* qw  = q_w    + (size_t)i * HD * HD;
        const float* qb  = q_b    + (size_t)i * HD;
        const float* kw  = k_w    + (size_t)i * HD * HD;
        const float* kb  = k_b    + (size_t)i * HD;
        const float* vw  = v_w    + (size_t)i * HD * HD;
        const float* vb  = v_b    + (size_t)i * HD;
        const float* ew  = e_w    + (size_t)i * D64 * HD;
        const float* sw  = skip_w + (size_t)i * HD * HD;
        const float* sb  = skip_b + (size_t)i * HD;
        const float* lw  = lin_w  + (size_t)i * HD * D64;
        const float* lb  = lin_b  + (size_t)i * D64;
        const float* f1w = ff_w1  + (size_t)i * D64 * 4 * D64;
        const float* f1b = ff_b1  + (size_t)i * 4 * D64;
        const float* f2w = ff_w2  + (size_t)i * 4 * D64 * D64;
        const float* f2b = ff_b2  + (size_t)i * D64;

        // weight precomputes (fp32, tiny)
        k_build_w2<<<CDIV(HD * HD, T), T, 0, st>>>(ew);
        k_build_w3<<<CDIV(HD * HD, T), T, 0, st>>>(ew);
        k_gemm2<HD, HD, 0, 0><<<dim3(1, 1), T, 0, st>>>(qw, w2_p, nullptr, qpw_p, HD, HD, HD);
        k_gemm2<HD, D64, 0, 0><<<dim3(1, 1), T, 0, st>>>(sw, lw, nullptr, swlw_p, D64, HD, D64);
        k_gemm2<HD, D64, 0, 0><<<dim3(1, 1), T, 0, st>>>(w3_p, lw, nullptr, lw3_p, D64, HD, D64);
        k_biaslin<<<1, 64, 0, st>>>(sb, lw, lb);
        k_wcat<<<CDIV(HD * 512, T), T, 0, st>>>(qw, kw, vw);
        k_bcat<<<2, 256, 0, st>>>(qb, kb, vb);
        k_wlin<<<CDIV(384 * D64, T), T, 0, st>>>(lw);

        // LN1 -> hn + big[:, :64]
        k_ln_stats<<<CDIV(NAUG * 32, T), T, 0, st>>>(h_p);
        k_ln_final<<<1, GG, 0, st>>>();
        k_ln_apply2<<<CDIV(NAUG * D64, T), T, 0, st>>>(h_p);

        // gen_conv -> agg ; gemm -> big[:, 64:128]
        k_gen<<<CDIV(NN * 32, T), T, 0, st>>>(edge_attr);
        k_gen_v<<<GG, T, 0, st>>>(edge_attr);
        k_gemm_tc<0, 0><<<dim3(GRID_N, 1), T, GEMM_SMEM, st>>>(agg_p, D64, gw, D64, gb,
                                                               big_p + 64, 384, NAUG, D64);

        // fused q|k|v|qp projection
        k_gemm_tc<0, 0><<<dim3(GRID_N, 8), T, GEMM_SMEM, st>>>(big_p, 384, wcat_p, 512, bcat_p,
                                                               qkvp_p, 512, NAUG, HD);

        // fused single-pass attention -> big[:, 128:256] (t), big[:, 256:384] (we)
        k_attn<<<CDIV(NN * 32, T), T, 0, st>>>(edge_attr);
        k_attn_v<<<GG, T, 0, st>>>(edge_attr);

        // lh = big @ wlin + blb  (one GEMM for skip + lin + edge terms)
        k_gemm_tc<0, 0><<<dim3(GRID_N, 1), T, GEMM_SMEM, st>>>(big_p, 384, wlin_p, D64, blb_p,
                                                               lh_p, D64, NAUG, 384);

        // LN2
        k_ln_stats<<<CDIV(NAUG * 32, T), T, 0, st>>>(lh_p);
        k_ln_final<<<1, GG, 0, st>>>();
        k_ln_apply<<<CDIV(NAUG * D64, T), T, 0, st>>>(lh_p, ln2_p);

        // FF + residual
        k_gemm_tc<1, 0><<<dim3(GRID_N, 4), T, GEMM_SMEM, st>>>(ln2_p, D64, f1w, 256, f1b,
                                                               ffh_p, 256, NAUG, D64);
        k_gemm_tc<0, 1><<<dim3(GRID_N, 1), T, GEMM_SMEM, st>>>(ffh_p, 256, f2w, D64, f2b,
                                                               h_p, D64, NAUG, 256);
    }

    // ---- outputs ----
    cudaMemcpyAsync(out, h_p, sizeof(float) * NN * D64, cudaMemcpyDeviceToDevice, st);
    k_glob_sum<<<CDIV(NN * D64, T), T, 0, st>>>(batch);
    k_glob_out<<<CDIV(GG * D64, T), T, 0, st>>>(out);
    k_ne_out<<<CDIV(NE_ * D64, T), T, 0, st>>>(ne_index, ne_index + NE_, out);
    k_cleanup<<<CDIV(GG * D64, T), T, 0, st>>>();
}

// round 6
// speedup vs baseline: 2.0388x; 1.0901x over previous
#include <cuda_runtime.h>
#include <cuda_bf16.h>
#include <math.h>
#include <stdint.h>

// Problem constants
#define D64   64
#define HH    2
#define HD    128
#define LL    3
#define NN    50000
#define GG    128
#define EE    600000
#define NE_   300000
#define NAUG  (NN + GG)          // 50128
#define M0    (EE + 2 * NN)      // 700000
#define MM    (M0 + NAUG)        // 750128
#define TAILR (MM - EE)          // 150128
#define NB_SCAN ((NAUG + 255) / 256)   // 196

#define CDIV(a, b) (((a) + (b) - 1) / (b))

// ---------------- device scratch (static, no allocs) ----------------
__device__ int    g_src[MM];
__device__ int    g_dst[MM];
__device__ int    g_deg[NAUG];
__device__ int    g_rowptr[NAUG + 1];
__device__ int    g_bsum[256];
__device__ int    g_fill[NAUG];
__device__ int    g_esrc[MM];
__device__ int    g_eid[MM];
__device__ float  g_eperm[(size_t)MM * D64];     // e_aug rows in CSR order
__device__ float  g_tail[(size_t)TAILR * D64];   // e_aug rows >= EE
__device__ float  g_h[NAUG * D64];
__device__ float  g_hn[NAUG * D64];
__device__ float  g_agg[NAUG * D64];
__device__ float  g_big[(size_t)NAUG * 384];     // [cat(128) | t(128) | we(128)]
__device__ float  g_qkvp[(size_t)NAUG * 512];    // [q | k | v | qp]
__device__ float  g_lh[NAUG * D64];
__device__ float  g_ln2[NAUG * D64];
__device__ float  g_ffh[(size_t)NAUG * 256];
__device__ float  g_w2[HD * HD];
__device__ float  g_w3[HD * HD];
__device__ float  g_qpw[HD * HD];
__device__ float  g_swlw[HD * D64];
__device__ float  g_lw3[HD * D64];
__device__ float  g_wcat[HD * 512];
__device__ float  g_bcat[512];
__device__ float  g_wlin[384 * D64];
__device__ float  g_blb[D64];
__device__ float  g_cntn[GG];
__device__ double g_lsum[GG];
__device__ double g_lsumsq[GG];
__device__ float  g_mean[GG];
__device__ float  g_rstd[GG];
__device__ int    g_abatch[NAUG];
__device__ float  g_gsum[GG * D64];

// ---------------- setup kernels ----------------
__global__ void k_build_edges(const int* __restrict__ ei0, const int* __restrict__ ei1,
                              const int* __restrict__ batch) {
    int m = blockIdx.x * blockDim.x + threadIdx.x;
    if (m >= MM) return;
    int s, d;
    if (m < EE)               { s = ei0[m]; d = ei1[m]; }
    else if (m < EE + NN)     { int i = m - EE;          s = i;             d = batch[i] + NN; }
    else if (m < EE + 2 * NN) { int i = m - EE - NN;     s = batch[i] + NN; d = i; }
    else                      { int i = m - EE - 2 * NN; s = i;             d = i; }
    g_src[m] = s; g_dst[m] = d;
    atomicAdd(&g_deg[d], 1);
}

__global__ void k_scanA() {
    __shared__ int sh[256];
    int t = threadIdx.x;
    int i = blockIdx.x * 256 + t;
    int v = (i < NAUG) ? g_deg[i] : 0;
    sh[t] = v;
    __syncthreads();
    for (int off = 1; off < 256; off <<= 1) {
        int a = (t >= off) ? sh[t - off] : 0;
        __syncthreads();
        sh[t] += a;
        __syncthreads();
    }
    if (i < NAUG) g_rowptr[i] = sh[t] - v;
    if (t == 255) g_bsum[blockIdx.x] = sh[255];
}

__global__ void k_scanB() {
    __shared__ int sh[256];
    int t = threadIdx.x;
    int v = (t < NB_SCAN) ? g_bsum[t] : 0;
    sh[t] = v;
    __syncthreads();
    for (int off = 1; off < 256; off <<= 1) {
        int a = (t >= off) ? sh[t - off] : 0;
        __syncthreads();
        sh[t] += a;
        __syncthreads();
    }
    if (t < NB_SCAN) g_bsum[t] = sh[t] - v;
}

__global__ void k_scanC() {
    int i = blockIdx.x * 256 + threadIdx.x;
    if (i < NAUG) {
        int r = g_rowptr[i] + g_bsum[i >> 8];
        g_rowptr[i] = r;
        g_fill[i] = r;
        g_deg[i] = 0;                 // self-clean
    }
    if (i == 0) g_rowptr[NAUG] = MM;
}

__global__ void k_scatter() {
    int m = blockIdx.x * blockDim.x + threadIdx.x;
    if (m >= MM) return;
    int pos = atomicAdd(&g_fill[g_dst[m]], 1);
    g_esrc[pos] = g_src[m];
    g_eid[pos]  = m;
}

__global__ void k_abatch(const int* __restrict__ batch) {
    int i = blockIdx.x * blockDim.x + threadIdx.x;
    if (i >= NAUG) return;
    g_abatch[i] = (i < NN) ? batch[i] : (i - NN);
}

__global__ void k_cntn(const int* __restrict__ batch) {
    int i = blockIdx.x * blockDim.x + threadIdx.x;
    if (i >= NN) return;
    atomicAdd(&g_cntn[batch[i]], 1.f);
}

__global__ void k_init_h(const float* __restrict__ x, const float* __restrict__ cond) {
    int idx = blockIdx.x * blockDim.x + threadIdx.x;
    if (idx >= NAUG * D64) return;
    g_h[idx] = (idx < NN * D64) ? x[idx] : cond[idx - NN * D64];
}

__global__ void k_tail_ep() {
    int idx = blockIdx.x * blockDim.x + threadIdx.x;
    if (idx >= 2 * NN * D64) return;
    g_tail[idx] = ((idx & 63) == 0) ? 1.f : 0.f;
}

__global__ void k_tail_csr(const float* __restrict__ edge_attr) {
    int i = (blockIdx.x * blockDim.x + threadIdx.x) >> 5;
    int lane = threadIdx.x & 31;
    if (i >= NAUG) return;
    float2 acc = {0.f, 0.f};
    float cnt = 0.f;
    int e0 = g_rowptr[i], e1 = g_rowptr[i + 1];
    for (int e = e0; e < e1; e++) {
        int m = g_eid[e];
        if (m < EE) {
            float2 ev = ((const float2*)(edge_attr + (size_t)m * D64))[lane];
            acc.x += ev.x; acc.y += ev.y;
            cnt += 1.f;
        } else if (m < M0) {
            if (lane == 0) acc.x += 1.f;
            cnt += 1.f;
        }
    }
    float invc = 1.f / fmaxf(cnt, 1.f);
    float2 o = {acc.x * invc, acc.y * invc};
    ((float2*)(g_tail + (size_t)(2 * NN + i) * D64))[lane] = o;
}

// permute e_aug rows into CSR order (sequential reads for all later edge sweeps)
__global__ void k_eperm(const float* __restrict__ edge_attr) {
    int gw = (blockIdx.x * blockDim.x + threadIdx.x) >> 5;
    int lane = threadIdx.x & 31;
    if (gw >= MM) return;
    int m = g_eid[gw];
    const float* ep = (m < EE) ? edge_attr + (size_t)m * D64
                               : g_tail + (size_t)(m - EE) * D64;
    float2 v = ((const float2*)ep)[lane];
    ((float2*)(g_eperm + (size_t)gw * D64))[lane] = v;
}

// ---------------- graph layernorm ----------------
__global__ void k_ln_stats(const float* __restrict__ X) {
    int i = (blockIdx.x * blockDim.x + threadIdx.x) >> 5;
    int lane = threadIdx.x & 31;
    if (i >= NAUG) return;
    float2 v = ((const float2*)(X + (size_t)i * D64))[lane];
    float s  = v.x + v.y;
    float ss = v.x * v.x + v.y * v.y;
#pragma unroll
    for (int off = 16; off; off >>= 1) {
        s  += __shfl_xor_sync(0xffffffffu, s, off);
        ss += __shfl_xor_sync(0xffffffffu, ss, off);
    }
    if (lane == 0) {
        int b = g_abatch[i];
        atomicAdd(&g_lsum[b], (double)s);
        atomicAdd(&g_lsumsq[b], (double)ss);
    }
}

__global__ void k_ln_final() {
    int g = threadIdx.x;
    if (g >= GG) return;
    double norm = (double)fmaxf(g_cntn[g] + 1.f, 1.f) * D64;
    double mean = g_lsum[g] / norm;
    double var  = g_lsumsq[g] / norm - mean * mean;
    g_mean[g] = (float)mean;
    g_rstd[g] = rsqrtf((float)var + 1e-5f);
    g_lsum[g] = 0.0;            // self-clean
    g_lsumsq[g] = 0.0;
}

// writes hn AND big[:, 0:64] (cat left half)
__global__ void k_ln_apply2(const float* __restrict__ X) {
    int idx = blockIdx.x * blockDim.x + threadIdx.x;
    if (idx >= NAUG * D64) return;
    int i = idx >> 6, d = idx & 63;
    int b = g_abatch[i];
    float v = (X[idx] - g_mean[b]) * g_rstd[b];
    g_hn[idx] = v;
    g_big[(size_t)i * 384 + d] = v;
}

__global__ void k_ln_apply(const float* __restrict__ X, float* __restrict__ Y) {
    int idx = blockIdx.x * blockDim.x + threadIdx.x;
    if (idx >= NAUG * D64) return;
    int b = g_abatch[idx >> 6];
    Y[idx] = (X[idx] - g_mean[b]) * g_rstd[b];
}

// ---------------- gen_conv: regular nodes (warp each), e sequential ----------------
__global__ void k_gen() {
    int i = (blockIdx.x * blockDim.x + threadIdx.x) >> 5;
    int lane = threadIdx.x & 31;
    if (i >= NN) return;
    float2 acc = {0.f, 0.f};
    int e0 = g_rowptr[i], e1 = g_rowptr[i + 1];
    for (int e = e0; e < e1; e++) {
        int s = g_esrc[e];
        float2 ev = ((const float2*)(g_eperm + (size_t)e * D64))[lane];
        float2 hv = ((const float2*)(g_hn + (size_t)s * D64))[lane];
        acc.x += fmaxf(hv.x + ev.x, 0.f) + 1e-7f;
        acc.y += fmaxf(hv.y + ev.y, 0.f) + 1e-7f;
    }
    float2 hi = ((const float2*)(g_hn + (size_t)i * D64))[lane];
    float2 o = {acc.x + hi.x, acc.y + hi.y};
    ((float2*)(g_agg + (size_t)i * D64))[lane] = o;
}

__global__ void k_gen_v() {
    __shared__ float sa[64];
    int i = NN + blockIdx.x;
    int tid = threadIdx.x, lane = tid & 31, wid = tid >> 5;
    if (tid < 64) sa[tid] = 0.f;
    __syncthreads();
    int e0 = g_rowptr[i], e1 = g_rowptr[i + 1];
    float2 acc = {0.f, 0.f};
    for (int e = e0 + wid; e < e1; e += 8) {
        int s = g_esrc[e];
        float2 ev = ((const float2*)(g_eperm + (size_t)e * D64))[lane];
        float2 hv = ((const float2*)(g_hn + (size_t)s * D64))[lane];
        acc.x += fmaxf(hv.x + ev.x, 0.f) + 1e-7f;
        acc.y += fmaxf(hv.y + ev.y, 0.f) + 1e-7f;
    }
    atomicAdd(&sa[2 * lane],     acc.x);
    atomicAdd(&sa[2 * lane + 1], acc.y);
    __syncthreads();
    if (tid < 64) g_agg[(size_t)i * D64 + tid] = sa[tid] + g_hn[(size_t)i * D64 + tid];
}

// ---------------- fused single-pass attention (online softmax), e sequential ----------------
__global__ void k_attn() {
    int i = (blockIdx.x * blockDim.x + threadIdx.x) >> 5;
    int lane = threadIdx.x & 31;
    if (i >= NN) return;
    int el = lane & 15;
    float4 q4  = *(const float4*)(g_qkvp + (size_t)i * 512 + 4 * lane);
    float4 qp4 = *(const float4*)(g_qkvp + (size_t)i * 512 + 384 + 4 * lane);
    int e0 = g_rowptr[i], e1 = g_rowptr[i + 1];
    float mx = -INFINITY, sum = 0.f;
    float4 vacc = {0.f, 0.f, 0.f, 0.f};
    float4 eacc = {0.f, 0.f, 0.f, 0.f};
    for (int e = e0; e < e1; e++) {
        int s = g_esrc[e];
        const float* ep = g_eperm + (size_t)e * D64;
        float4 k4 = *(const float4*)(g_qkvp + (size_t)s * 512 + 128 + 4 * lane);
        float4 e4 = *(const float4*)(ep + 4 * el);
        float p = q4.x * k4.x + q4.y * k4.y + q4.z * k4.z + q4.w * k4.w
                + qp4.x * e4.x + qp4.y * e4.y + qp4.z * e4.z + qp4.w * e4.w;
        p += __shfl_xor_sync(0xffffffffu, p, 1);
        p += __shfl_xor_sync(0xffffffffu, p, 2);
        p += __shfl_xor_sync(0xffffffffu, p, 4);
        p += __shfl_xor_sync(0xffffffffu, p, 8);
        float a = p * 0.125f;
        if (a > mx) {
            float sc = expf(mx - a);
            sum *= sc;
            vacc.x *= sc; vacc.y *= sc; vacc.z *= sc; vacc.w *= sc;
            eacc.x *= sc; eacc.y *= sc; eacc.z *= sc; eacc.w *= sc;
            mx = a;
        }
        float w = expf(a - mx);
        sum += w;
        float4 v4 = *(const float4*)(g_qkvp + (size_t)s * 512 + 256 + 4 * lane);
        vacc.x += w * v4.x; vacc.y += w * v4.y; vacc.z += w * v4.z; vacc.w += w * v4.w;
        eacc.x += w * e4.x; eacc.y += w * e4.y; eacc.z += w * e4.z; eacc.w += w * e4.w;
    }
    float inv = 1.f / (sum + 1e-16f);
    float4 to = {vacc.x * inv, vacc.y * inv, vacc.z * inv, vacc.w * inv};
    float4 wo = {eacc.x * inv, eacc.y * inv, eacc.z * inv, eacc.w * inv};
    *(float4*)(g_big + (size_t)i * 384 + 128 + 4 * lane) = to;
    *(float4*)(g_big + (size_t)i * 384 + 256 + 4 * lane) = wo;
}

__global__ void k_attn_v() {
    __shared__ float sv[128];
    __shared__ float se[128];
    __shared__ float ssg[2];
    __shared__ float swmx[16];
    __shared__ float gmx[2];
    int i = NN + blockIdx.x;
    int tid = threadIdx.x, lane = tid & 31, wid = tid >> 5;
    int el = lane & 15;
    int hh = lane >> 4;
    if (tid < 128) { sv[tid] = 0.f; se[tid] = 0.f; }
    if (tid < 2) ssg[tid] = 0.f;
    __syncthreads();
    float4 q4  = *(const float4*)(g_qkvp + (size_t)i * 512 + 4 * lane);
    float4 qp4 = *(const float4*)(g_qkvp + (size_t)i * 512 + 384 + 4 * lane);
    int e0 = g_rowptr[i], e1 = g_rowptr[i + 1];
    float mx = -INFINITY, sum = 0.f;
    float4 vacc = {0.f, 0.f, 0.f, 0.f};
    float4 eacc = {0.f, 0.f, 0.f, 0.f};
    for (int e = e0 + wid; e < e1; e += 8) {
        int s = g_esrc[e];
        const float* ep = g_eperm + (size_t)e * D64;
        float4 k4 = *(const float4*)(g_qkvp + (size_t)s * 512 + 128 + 4 * lane);
        float4 e4 = *(const float4*)(ep + 4 * el);
        float p = q4.x * k4.x + q4.y * k4.y + q4.z * k4.z + q4.w * k4.w
                + qp4.x * e4.x + qp4.y * e4.y + qp4.z * e4.z + qp4.w * e4.w;
        p += __shfl_xor_sync(0xffffffffu, p, 1);
        p += __shfl_xor_sync(0xffffffffu, p, 2);
        p += __shfl_xor_sync(0xffffffffu, p, 4);
        p += __shfl_xor_sync(0xffffffffu, p, 8);
        float a = p * 0.125f;
        if (a > mx) {
            float sc = expf(mx - a);
            sum *= sc;
            vacc.x *= sc; vacc.y *= sc; vacc.z *= sc; vacc.w *= sc;
            eacc.x *= sc; eacc.y *= sc; eacc.z *= sc; eacc.w *= sc;
            mx = a;
        }
        float w = expf(a - mx);
        sum += w;
        float4 v4 = *(const float4*)(g_qkvp + (size_t)s * 512 + 256 + 4 * lane);
        vacc.x += w * v4.x; vacc.y += w * v4.y; vacc.z += w * v4.z; vacc.w += w * v4.w;
        eacc.x += w * e4.x; eacc.y += w * e4.y; eacc.z += w * e4.z; eacc.w += w * e4.w;
    }
    if (el == 0) swmx[wid * 2 + hh] = mx;
    __syncthreads();
    if (tid < 2) {
        float m = -INFINITY;
#pragma unroll
        for (int w = 0; w < 8; w++) m = fmaxf(m, swmx[w * 2 + tid]);
        gmx[tid] = m;
    }
    __syncthreads();
    float sc = expf(mx - gmx[hh]);
    atomicAdd(&sv[4 * lane],     vacc.x * sc); atomicAdd(&sv[4 * lane + 1], vacc.y * sc);
    atomicAdd(&sv[4 * lane + 2], vacc.z * sc); atomicAdd(&sv[4 * lane + 3], vacc.w * sc);
    atomicAdd(&se[4 * lane],     eacc.x * sc); atomicAdd(&se[4 * lane + 1], eacc.y * sc);
    atomicAdd(&se[4 * lane + 2], eacc.z * sc); atomicAdd(&se[4 * lane + 3], eacc.w * sc);
    if (el == 0) atomicAdd(&ssg[hh], sum * sc);
    __syncthreads();
    if (tid < 128) {
        float inv = 1.f / (ssg[tid >> 6] + 1e-16f);
        g_big[(size_t)i * 384 + 128 + tid] = sv[tid] * inv;
        g_big[(size_t)i * 384 + 256 + tid] = se[tid] * inv;
    }
}

// ---------------- block-diagonal weight builders ----------------
__global__ void k_build_w2(const float* __restrict__ ew) {
    int idx = blockIdx.x * blockDim.x + threadIdx.x;
    if (idx >= HD * HD) return;
    int r = idx >> 7, o = idx & 127;
    int h = r >> 6, d = r & 63, h2 = o >> 6, c = o & 63;
    g_w2[idx] = (h == h2) ? ew[(size_t)c * HD + h * 64 + d] : 0.f;
}
__global__ void k_build_w3(const float* __restrict__ ew) {
    int idx = blockIdx.x * blockDim.x + threadIdx.x;
    if (idx >= HD * HD) return;
    int r = idx >> 7, o = idx & 127;
    int h = r >> 6, c = r & 63, h2 = o >> 6, o2 = o & 63;
    g_w3[idx] = (h == h2) ? ew[(size_t)c * HD + h2 * 64 + o2] : 0.f;
}

__global__ void k_biaslin(const float* __restrict__ sb, const float* __restrict__ lw,
                          const float* __restrict__ lb) {
    int o = threadIdx.x;
    if (o >= D64) return;
    float acc = lb[o];
    for (int k2 = 0; k2 < HD; k2++) acc += sb[k2] * lw[(size_t)k2 * D64 + o];
    g_blb[o] = acc;
}

// wcat = [qw | kw | vw | qw@W2]  (128 x 512)
__global__ void k_wcat(const float* __restrict__ qw, const float* __restrict__ kw,
                       const float* __restrict__ vw) {
    int idx = blockIdx.x * blockDim.x + threadIdx.x;
    if (idx >= HD * 512) return;
    int r = idx >> 9, c = idx & 511;
    float v;
    if (c < 128)      v = qw[r * HD + c];
    else if (c < 256) v = kw[r * HD + c - 128];
    else if (c < 384) v = vw[r * HD + c - 256];
    else              v = g_qpw[r * HD + c - 384];
    g_wcat[idx] = v;
}

// bcat = [qb | kb | vb | qb@W2]
__global__ void k_bcat(const float* __restrict__ qb, const float* __restrict__ kb,
                       const float* __restrict__ vb) {
    int c = blockIdx.x * blockDim.x + threadIdx.x;
    if (c >= 512) return;
    float v;
    if (c < 128)      v = qb[c];
    else if (c < 256) v = kb[c - 128];
    else if (c < 384) v = vb[c - 256];
    else {
        int o = c - 384;
        float a = 0.f;
        for (int d = 0; d < HD; d++) a += qb[d] * g_w2[d * HD + o];
        v = a;
    }
    g_bcat[c] = v;
}

// wlin = [sw@lw ; lw ; W3@lw]  (384 x 64), matching big = [cat|t|we]
__global__ void k_wlin(const float* __restrict__ lw) {
    int idx = blockIdx.x * blockDim.x + threadIdx.x;
    if (idx >= 384 * D64) return;
    int r = idx >> 6, c = idx & 63;
    float v;
    if (r < 128)      v = g_swlw[r * D64 + c];
    else if (r < 256) v = lw[(size_t)(r - 128) * D64 + c];
    else              v = g_lw3[(r - 256) * D64 + c];
    g_wlin[idx] = v;
}

// ---------------- fp32 GEMM (weight prep only; rows ~128) ----------------
template <int IN, int OUTT, int ACT, int ACCUM>
__global__ __launch_bounds__(256) void k_gemm2(
        const float* __restrict__ A, const float* __restrict__ W,
        const float* __restrict__ bias, float* __restrict__ C,
        int ldc, int rows, int wld) {
    __shared__ float As[32][132];
    __shared__ float Ws[32][OUTT];
    constexpr int CT = OUTT / 16;
    const int tid = threadIdx.x;
    const int tx = tid & 15;
    const int ty = tid >> 4;
    const int r0 = blockIdx.x * 128;
    const int col0 = blockIdx.y * OUTT;
    float acc[8][CT];
#pragma unroll
    for (int i = 0; i < 8; i++)
#pragma unroll
        for (int j = 0; j < CT; j++) acc[i][j] = 0.f;

    for (int k0 = 0; k0 < IN; k0 += 32) {
#pragma unroll
        for (int t = 0; t < 4; t++) {
            int li = tid + t * 256;
            int r = li >> 3, kq = li & 7;
            int row = r0 + r;
            float4 av = make_float4(0.f, 0.f, 0.f, 0.f);
            if (row < rows) av = *(const float4*)(A + (size_t)row * IN + k0 + kq * 4);
            As[kq * 4 + 0][r] = av.x;
            As[kq * 4 + 1][r] = av.y;
            As[kq * 4 + 2][r] = av.z;
            As[kq * 4 + 3][r] = av.w;
        }
#pragma unroll
        for (int t = 0; t < OUTT / 32; t++) {
            int li = tid + t * 256;
            int kk = li / (OUTT / 4), oq = li % (OUTT / 4);
            ((float4*)(&Ws[kk][0]))[oq] =
                *(const float4*)(W + (size_t)(k0 + kk) * wld + col0 + oq * 4);
        }
        __syncthreads();
#pragma unroll
        for (int kk = 0; kk < 32; kk++) {
            float4 a0 = *(const float4*)&As[kk][ty * 8];
            float4 a1 = *(const float4*)&As[kk][ty * 8 + 4];
            float av[8] = {a0.x, a0.y, a0.z, a0.w, a1.x, a1.y, a1.z, a1.w};
            float wv[CT];
            float4 w0 = *(const float4*)&Ws[kk][tx * CT];
            wv[0] = w0.x; wv[1] = w0.y; wv[2] = w0.z; wv[3] = w0.w;
            if (CT == 8) {
                float4 w1 = *(const float4*)&Ws[kk][tx * CT + 4];
                wv[4] = w1.x; wv[5] = w1.y; wv[6] = w1.z; wv[7] = w1.w;
            }
#pragma unroll
            for (int i = 0; i < 8; i++)
#pragma unroll
                for (int j = 0; j < CT; j++) acc[i][j] += av[i] * wv[j];
        }
        __syncthreads();
    }
#pragma unroll
    for (int i = 0; i < 8; i++) {
        int row = r0 + ty * 8 + i;
        if (row >= rows) continue;
#pragma unroll
        for (int j = 0; j < CT; j++) {
            int col = col0 + tx * CT + j;
            float v = acc[i][j] + (bias ? bias[col] : 0.f);
            if (ACT == 1) v = (v > 0.f) ? v : 0.01f * v;
            float* cp = &C[(size_t)row * ldc + col];
            if (ACCUM) *cp += v; else *cp = v;
        }
    }
}

// ---------------- 3xBF16 tensor-core GEMM ----------------
__device__ __forceinline__ void mma16(float* c, uint32_t a0, uint32_t a1, uint32_t a2,
                                      uint32_t a3, uint32_t b0, uint32_t b1) {
    asm volatile(
        "mma.sync.aligned.m16n8k16.row.col.f32.bf16.bf16.f32 "
        "{%0,%1,%2,%3}, {%4,%5,%6,%7}, {%8,%9}, {%0,%1,%2,%3};"
        : "+f"(c[0]), "+f"(c[1]), "+f"(c[2]), "+f"(c[3])
        : "r"(a0), "r"(a1), "r"(a2), "r"(a3), "r"(b0), "r"(b1));
}

// C[rows x OUT] = act(A[rows x K](lda) @ W[K x OUT](wld) + bias)
// block: 256 thr = 8 warps (4 m x 2 n), tile 128 x 64, K step 32 (2 mma-k16 steps).
// fp32 -> bf16 hi/lo split done once in smem loaders. Row pad 40 => conflict-free frags.
template <int ACT, int ACCUM>
__global__ __launch_bounds__(256) void k_gemm_bf(
        const float* __restrict__ A, int lda,
        const float* __restrict__ W, int wld,
        const float* __restrict__ bias, float* __restrict__ C,
        int ldc, int rows, int K) {
    __shared__ __align__(16) __nv_bfloat16 Ah[128][40];
    __shared__ __align__(16) __nv_bfloat16 Al[128][40];
    __shared__ __align__(16) __nv_bfloat16 Wh[64][40];
    __shared__ __align__(16) __nv_bfloat16 Wl[64][40];
    const int tid = threadIdx.x, lane = tid & 31, warp = tid >> 5;
    const int warpM = warp & 3, warpN = warp >> 2;
    const int gid = lane >> 2, tig = lane & 3;
    const int r0 = blockIdx.x * 128, col0 = blockIdx.y * 64;
    float acc[2][4][4];
#pragma unroll
    for (int mt = 0; mt < 2; mt++)
#pragma unroll
        for (int nt = 0; nt < 4; nt++)
#pragma unroll
            for (int r = 0; r < 4; r++) acc[mt][nt][r] = 0.f;

    for (int k0 = 0; k0 < K; k0 += 32) {
        // A tile: split to bf16 hi/lo once per element
#pragma unroll
        for (int t = 0; t < 4; t++) {
            int li = tid + t * 256;
            int r = li >> 3, kq = li & 7;
            int row = r0 + r;
            float4 av = make_float4(0.f, 0.f, 0.f, 0.f);
            if (row < rows) av = *(const float4*)(A + (size_t)row * lda + k0 + kq * 4);
            __nv_bfloat16 h0 = __float2bfloat16_rn(av.x);
            __nv_bfloat16 h1 = __float2bfloat16_rn(av.y);
            __nv_bfloat16 h2 = __float2bfloat16_rn(av.z);
            __nv_bfloat16 h3 = __float2bfloat16_rn(av.w);
            Ah[r][kq * 4 + 0] = h0; Ah[r][kq * 4 + 1] = h1;
            Ah[r][kq * 4 + 2] = h2; Ah[r][kq * 4 + 3] = h3;
            Al[r][kq * 4 + 0] = __float2bfloat16_rn(av.x - __bfloat162float(h0));
            Al[r][kq * 4 + 1] = __float2bfloat16_rn(av.y - __bfloat162float(h1));
            Al[r][kq * 4 + 2] = __float2bfloat16_rn(av.z - __bfloat162float(h2));
            Al[r][kq * 4 + 3] = __float2bfloat16_rn(av.w - __bfloat162float(h3));
        }
        // W tile: transposed store Wt[n][k]
#pragma unroll
        for (int t = 0; t < 2; t++) {
            int li = tid + t * 256;
            int kk = li >> 4, oq = li & 15;
            float4 wv = *(const float4*)(W + (size_t)(k0 + kk) * wld + col0 + oq * 4);
            __nv_bfloat16 h0 = __float2bfloat16_rn(wv.x);
            __nv_bfloat16 h1 = __float2bfloat16_rn(wv.y);
            __nv_bfloat16 h2 = __float2bfloat16_rn(wv.z);
            __nv_bfloat16 h3 = __float2bfloat16_rn(wv.w);
            Wh[oq * 4 + 0][kk] = h0; Wh[oq * 4 + 1][kk] = h1;
            Wh[oq * 4 + 2][kk] = h2; Wh[oq * 4 + 3][kk] = h3;
            Wl[oq * 4 + 0][kk] = __float2bfloat16_rn(wv.x - __bfloat162float(h0));
            Wl[oq * 4 + 1][kk] = __float2bfloat16_rn(wv.y - __bfloat162float(h1));
            Wl[oq * 4 + 2][kk] = __float2bfloat16_rn(wv.z - __bfloat162float(h2));
            Wl[oq * 4 + 3][kk] = __float2bfloat16_rn(wv.w - __bfloat162float(h3));
        }
        __syncthreads();
#pragma unroll
        for (int ks = 0; ks < 2; ks++) {
            int kb = ks * 16;
            uint32_t ah[2][4], al[2][4];
#pragma unroll
            for (int mt = 0; mt < 2; mt++) {
                int ar = warpM * 32 + mt * 16 + gid;
                ah[mt][0] = *(const uint32_t*)&Ah[ar][kb + 2 * tig];
                ah[mt][1] = *(const uint32_t*)&Ah[ar + 8][kb + 2 * tig];
                ah[mt][2] = *(const uint32_t*)&Ah[ar][kb + 2 * tig + 8];
                ah[mt][3] = *(const uint32_t*)&Ah[ar + 8][kb + 2 * tig + 8];
                al[mt][0] = *(const uint32_t*)&Al[ar][kb + 2 * tig];
                al[mt][1] = *(const uint32_t*)&Al[ar + 8][kb + 2 * tig];
                al[mt][2] = *(const uint32_t*)&Al[ar][kb + 2 * tig + 8];
                al[mt][3] = *(const uint32_t*)&Al[ar + 8][kb + 2 * tig + 8];
            }
            uint32_t bh[4][2], bl[4][2];
#pragma unroll
            for (int nt = 0; nt < 4; nt++) {
                int bc = warpN * 32 + nt * 8 + gid;
                bh[nt][0] = *(const uint32_t*)&Wh[bc][kb + 2 * tig];
                bh[nt][1] = *(const uint32_t*)&Wh[bc][kb + 2 * tig + 8];
                bl[nt][0] = *(const uint32_t*)&Wl[bc][kb + 2 * tig];
                bl[nt][1] = *(const uint32_t*)&Wl[bc][kb + 2 * tig + 8];
            }
#pragma unroll
            for (int mt = 0; mt < 2; mt++)
#pragma unroll
                for (int nt = 0; nt < 4; nt++) {
                    mma16(acc[mt][nt], ah[mt][0], ah[mt][1], ah[mt][2], ah[mt][3],
                          bl[nt][0], bl[nt][1]);
                    mma16(acc[mt][nt], al[mt][0], al[mt][1], al[mt][2], al[mt][3],
                          bh[nt][0], bh[nt][1]);
                    mma16(acc[mt][nt], ah[mt][0], ah[mt][1], ah[mt][2], ah[mt][3],
                          bh[nt][0], bh[nt][1]);
                }
        }
        __syncthreads();
    }
    // epilogue
#pragma unroll
    for (int mt = 0; mt < 2; mt++) {
        int rl = r0 + warpM * 32 + mt * 16 + gid;
#pragma unroll
        for (int half = 0; half < 2; half++) {
            int row = rl + half * 8;
            if (row >= rows) continue;
#pragma unroll
            for (int nt = 0; nt < 4; nt++) {
                int col = col0 + warpN * 32 + nt * 8 + tig * 2;
                float v0 = acc[mt][nt][half * 2 + 0];
                float v1 = acc[mt][nt][half * 2 + 1];
                if (bias) { v0 += bias[col]; v1 += bias[col + 1]; }
                if (ACT == 1) {
                    v0 = (v0 > 0.f) ? v0 : 0.01f * v0;
                    v1 = (v1 > 0.f) ? v1 : 0.01f * v1;
                }
                float2* cp = (float2*)(C + (size_t)row * ldc + col);
                if (ACCUM) { float2 o = *cp; v0 += o.x; v1 += o.y; }
                *cp = make_float2(v0, v1);
            }
        }
    }
}

// ---------------- outputs ----------------
__global__ void k_glob_sum(const int* __restrict__ batch) {
    int idx = blockIdx.x * blockDim.x + threadIdx.x;
    if (idx >= NN * D64) return;
    atomicAdd(&g_gsum[batch[idx >> 6] * D64 + (idx & 63)], g_h[idx]);
}

__global__ void k_glob_out(float* __restrict__ out) {
    int idx = blockIdx.x * blockDim.x + threadIdx.x;
    if (idx >= GG * D64) return;
    int g = idx >> 6;
    out[NN * D64 + idx] = g_gsum[idx] / fmaxf(g_cntn[g], 1.f) + g_h[NN * D64 + idx];
}

__global__ void k_ne_out(const int* __restrict__ ne0, const int* __restrict__ ne1,
                         float* __restrict__ out) {
    int idx = blockIdx.x * blockDim.x + threadIdx.x;
    if (idx >= NE_ * D64) return;
    int j = idx >> 6, d = idx & 63;
    out[(NN + GG) * D64 + idx] = g_h[ne0[j] * D64 + d] + g_h[ne1[j] * D64 + d];
}

__global__ void k_cleanup() {
    int idx = blockIdx.x * blockDim.x + threadIdx.x;
    if (idx < GG * D64) g_gsum[idx] = 0.f;
    if (idx < GG) g_cntn[idx] = 0.f;
}

// ---------------- host launcher ----------------
#define GETSYM(ptr, sym) do { void* _p; cudaGetSymbolAddress(&_p, sym); ptr = (decltype(ptr))_p; } while (0)

extern "C" void kernel_launch(void* const* d_in, const int* in_sizes, int n_in,
                              void* d_out, int out_size) {
    const float* x          = (const float*)d_in[0];
    const float* cond       = (const float*)d_in[1];
    const float* edge_attr  = (const float*)d_in[2];
    const int*   edge_index = (const int*)d_in[3];
    const int*   ne_index   = (const int*)d_in[4];
    const int*   batch      = (const int*)d_in[5];
    const float* gen_w  = (const float*)d_in[6];
    const float* gen_b  = (const float*)d_in[7];
    const float* q_w    = (const float*)d_in[8];
    const float* q_b    = (const float*)d_in[9];
    const float* k_w    = (const float*)d_in[10];
    const float* k_b    = (const float*)d_in[11];
    const float* v_w    = (const float*)d_in[12];
    const float* v_b    = (const float*)d_in[13];
    const float* e_w    = (const float*)d_in[14];
    const float* skip_w = (const float*)d_in[15];
    const float* skip_b = (const float*)d_in[16];
    const float* lin_w  = (const float*)d_in[17];
    const float* lin_b  = (const float*)d_in[18];
    const float* ff_w1  = (const float*)d_in[19];
    const float* ff_b1  = (const float*)d_in[20];
    const float* ff_w2  = (const float*)d_in[21];
    const float* ff_b2  = (const float*)d_in[22];
    float* out = (float*)d_out;

    float *h_p, *agg_p, *big_p, *qkvp_p, *lh_p, *ln2_p, *ffh_p;
    float *w2_p, *w3_p, *qpw_p, *swlw_p, *lw3_p, *wcat_p, *bcat_p, *wlin_p, *blb_p;
    GETSYM(h_p, g_h);       GETSYM(agg_p, g_agg);
    GETSYM(big_p, g_big);   GETSYM(qkvp_p, g_qkvp); GETSYM(lh_p, g_lh);
    GETSYM(ln2_p, g_ln2);   GETSYM(ffh_p, g_ffh);
    GETSYM(w2_p, g_w2);     GETSYM(w3_p, g_w3);     GETSYM(qpw_p, g_qpw);
    GETSYM(swlw_p, g_swlw); GETSYM(lw3_p, g_lw3);   GETSYM(wcat_p, g_wcat);
    GETSYM(bcat_p, g_bcat); GETSYM(wlin_p, g_wlin); GETSYM(blb_p, g_blb);

    const int T = 256;
    const int GRID_N = CDIV(NAUG, 128);
    cudaStream_t st = 0;

    // ---- setup ----
    k_build_edges<<<CDIV(MM, T), T, 0, st>>>(edge_index, edge_index + EE, batch);
    k_scanA<<<NB_SCAN, 256, 0, st>>>();
    k_scanB<<<1, 256, 0, st>>>();
    k_scanC<<<NB_SCAN, 256, 0, st>>>();
    k_scatter<<<CDIV(MM, T), T, 0, st>>>();
    k_abatch<<<CDIV(NAUG, T), T, 0, st>>>(batch);
    k_cntn<<<CDIV(NN, T), T, 0, st>>>(batch);
    k_init_h<<<CDIV(NAUG * D64, T), T, 0, st>>>(x, cond);
    k_tail_ep<<<CDIV(2 * NN * D64, T), T, 0, st>>>();
    k_tail_csr<<<CDIV(NAUG * 32, T), T, 0, st>>>(edge_attr);
    k_eperm<<<CDIV(MM * 32, T), T, 0, st>>>(edge_attr);

    // ---- layers ----
    for (int i = 0; i < LL; i++) {
        const float* gw  = gen_w  + (size_t)i * D64 * D64;
        const float* gb  = gen_b  + (size_t)i * D64;
        const float* qw  = q_w    + (size_t)i * HD * HD;
        const float* qb  = q_b    + (size_t)i * HD;
        const float* kw  = k_w    + (size_t)i * HD * HD;
        const float* kb  = k_b    + (size_t)i * HD;
        const float* vw  = v_w    + (size_t)i * HD * HD;
        const float* vb  = v_b    + (size_t)i * HD;
        const float* ew  = e_w    + (size_t)i * D64 * HD;
        const float* sw  = skip_w + (size_t)i * HD * HD;
        const float* sb  = skip_b + (size_t)i * HD;
        const float* lw  = lin_w  + (size_t)i * HD * D64;
        const float* lb  = lin_b  + (size_t)i * D64;
        const float* f1w = ff_w1  + (size_t)i * D64 * 4 * D64;
        const float* f1b = ff_b1  + (size_t)i * 4 * D64;
        const float* f2w = ff_w2  + (size_t)i * 4 * D64 * D64;
        const float* f2b = ff_b2  + (size_t)i * D64;

        // weight precomputes (fp32, tiny)
        k_build_w2<<<CDIV(HD * HD, T), T, 0, st>>>(ew);
        k_build_w3<<<CDIV(HD * HD, T), T, 0, st>>>(ew);
        k_gemm2<HD, HD, 0, 0><<<dim3(1, 1), T, 0, st>>>(qw, w2_p, nullptr, qpw_p, HD, HD, HD);
        k_gemm2<HD, D64, 0, 0><<<dim3(1, 1), T, 0, st>>>(sw, lw, nullptr, swlw_p, D64, HD, D64);
        k_gemm2<HD, D64, 0, 0><<<dim3(1, 1), T, 0, st>>>(w3_p, lw, nullptr, lw3_p, D64, HD, D64);
        k_biaslin<<<1, 64, 0, st>>>(sb, lw, lb);
        k_wcat<<<CDIV(HD * 512, T), T, 0, st>>>(qw, kw, vw);
        k_bcat<<<2, 256, 0, st>>>(qb, kb, vb);
        k_wlin<<<CDIV(384 * D64, T), T, 0, st>>>(lw);

        // LN1 -> hn + big[:, :64]
        k_ln_stats<<<CDIV(NAUG * 32, T), T, 0, st>>>(h_p);
        k_ln_final<<<1, GG, 0, st>>>();
        k_ln_apply2<<<CDIV(NAUG * D64, T), T, 0, st>>>(h_p);

        // gen_conv -> agg ; gemm -> big[:, 64:128]
        k_gen<<<CDIV(NN * 32, T), T, 0, st>>>();
        k_gen_v<<<GG, T, 0, st>>>();
        k_gemm_bf<0, 0><<<dim3(GRID_N, 1), T, 0, st>>>(agg_p, D64, gw, D64, gb,
                                                       big_p + 64, 384, NAUG, D64);

        // fused q|k|v|qp projection
        k_gemm_bf<0, 0><<<dim3(GRID_N, 8), T, 0, st>>>(big_p, 384, wcat_p, 512, bcat_p,
                                                       qkvp_p, 512, NAUG, HD);

        // fused single-pass attention -> big[:, 128:256] (t), big[:, 256:384] (we)
        k_attn<<<CDIV(NN * 32, T), T, 0, st>>>();
        k_attn_v<<<GG, T, 0, st>>>();

        // lh = big @ wlin + blb
        k_gemm_bf<0, 0><<<dim3(GRID_N, 1), T, 0, st>>>(big_p, 384, wlin_p, D64, blb_p,
                                                       lh_p, D64, NAUG, 384);

        // LN2
        k_ln_stats<<<CDIV(NAUG * 32, T), T, 0, st>>>(lh_p);
        k_ln_final<<<1, GG, 0, st>>>();
        k_ln_apply<<<CDIV(NAUG * D64, T), T, 0, st>>>(lh_p, ln2_p);

        // FF + residual
        k_gemm_bf<1, 0><<<dim3(GRID_N, 4), T, 0, st>>>(ln2_p, D64, f1w, 256, f1b,
                                                       ffh_p, 256, NAUG, D64);
        k_gemm_bf<0, 1><<<dim3(GRID_N, 1), T, 0, st>>>(ffh_p, 256, f2w, D64, f2b,
                                                       h_p, D64, NAUG, 256);
    }

    // ---- outputs ----
    cudaMemcpyAsync(out, h_p, sizeof(float) * NN * D64, cudaMemcpyDeviceToDevice, st);
    k_glob_sum<<<CDIV(NN * D64, T), T, 0, st>>>(batch);
    k_glob_out<<<CDIV(GG * D64, T), T, 0, st>>>(out);
    k_ne_out<<<CDIV(NE_ * D64, T), T, 0, st>>>(ne_index, ne_index + NE_, out);
    k_cleanup<<<CDIV(GG * D64, T), T, 0, st>>>();
}